// round 1
// baseline (speedup 1.0000x reference)
#include <cuda_runtime.h>

// Problem constants (from reference): S=2048, B=2, HQ=32, HKV=8, D=128
#define S_LEN 2048
#define BATCH 2
#define HQ 32
#define HKV 8
#define DH 128
#define GROUP (HQ / HKV)      // 4
#define SCALE 0.08838834764831845f  // 1/sqrt(128)

#define BM 64                 // query tile
#define BN 64                 // key tile
#define PADR 132              // padded floats per 128-float row (2-way max conflicts, 16B aligned)
#define PADS 68               // padded floats per 64-float score row
#define NTHREADS 256

// smem layout (floats):
//   sQ : BM*PADR      (Q tile, pre-scaled)
//   sK : BN*PADR
//   sV : BN*PADR
//   sS : BM*PADS      (scores -> probabilities)
//   sM : BM  (running max)  sL : BM (running sum)  sF : BM (rescale factor)
#define SMEM_FLOATS (3 * BM * PADR + BM * PADS + 3 * BM)

__global__ void __launch_bounds__(NTHREADS, 1)
fa_fp32_kernel(const float* __restrict__ Q,
               const float* __restrict__ K,
               const float* __restrict__ V,
               float* __restrict__ O)
{
    extern __shared__ float smem[];
    float* sQ = smem;
    float* sK = sQ + BM * PADR;
    float* sV = sK + BN * PADR;
    float* sS = sV + BN * PADR;
    float* sM = sS + BM * PADS;
    float* sL = sM + BM;
    float* sF = sL + BM;

    const int tid = threadIdx.x;
    // Heaviest (largest) q-blocks first to reduce wave-tail imbalance.
    const int qblock = (S_LEN / BM - 1) - blockIdx.x;
    const int h = blockIdx.y;
    const int b = blockIdx.z;
    const int hk = h / GROUP;
    const int qbase = qblock * BM;

    const int ty = tid >> 4;   // 0..15 : row group
    const int tx = tid & 15;   // 0..15 : col group

    const long qstride = (long)BATCH * HQ * DH;   // floats per seq step (Q/O)
    const long kstride = (long)BATCH * HKV * DH;  // floats per seq step (K/V)

    // ---- Load Q tile (pre-scaled by SCALE) ----
    {
        const float* qg = Q + (long)qbase * qstride + (long)b * HQ * DH + (long)h * DH;
        #pragma unroll
        for (int e = tid; e < BM * 32; e += NTHREADS) {
            int r = e >> 5, c4 = e & 31;
            float4 v = *(const float4*)(qg + (long)r * qstride + c4 * 4);
            v.x *= SCALE; v.y *= SCALE; v.z *= SCALE; v.w *= SCALE;
            *(float4*)(sQ + r * PADR + c4 * 4) = v;
        }
        if (tid < BM) { sM[tid] = -1e30f; sL[tid] = 0.0f; }
    }

    float acc[4][8];
    #pragma unroll
    for (int r = 0; r < 4; r++)
        #pragma unroll
        for (int c = 0; c < 8; c++) acc[r][c] = 0.0f;

    const float* kg0 = K + (long)b * HKV * DH + (long)hk * DH;
    const float* vg0 = V + (long)b * HKV * DH + (long)hk * DH;

    for (int kt = 0; kt <= qblock; ++kt) {
        __syncthreads();  // protect sK/sV/sS from previous iteration readers
        const int kbase = kt * BN;

        // ---- Load K,V tiles ----
        #pragma unroll
        for (int e = tid; e < BN * 32; e += NTHREADS) {
            int r = e >> 5, c4 = e & 31;
            *(float4*)(sK + r * PADR + c4 * 4) =
                *(const float4*)(kg0 + (long)(kbase + r) * kstride + c4 * 4);
            *(float4*)(sV + r * PADR + c4 * 4) =
                *(const float4*)(vg0 + (long)(kbase + r) * kstride + c4 * 4);
        }
        __syncthreads();

        // ---- S = Q K^T  (each thread: 4x4 micro-tile) ----
        float sc[4][4];
        #pragma unroll
        for (int r = 0; r < 4; r++)
            #pragma unroll
            for (int c = 0; c < 4; c++) sc[r][c] = 0.0f;

        #pragma unroll 8
        for (int d4 = 0; d4 < 32; ++d4) {
            float4 qv[4], kv[4];
            #pragma unroll
            for (int r = 0; r < 4; r++)
                qv[r] = *(float4*)(sQ + (ty * 4 + r) * PADR + d4 * 4);
            #pragma unroll
            for (int c = 0; c < 4; c++)
                kv[c] = *(float4*)(sK + (tx * 4 + c) * PADR + d4 * 4);
            #pragma unroll
            for (int r = 0; r < 4; r++)
                #pragma unroll
                for (int c = 0; c < 4; c++) {
                    sc[r][c] += qv[r].x * kv[c].x;
                    sc[r][c] += qv[r].y * kv[c].y;
                    sc[r][c] += qv[r].z * kv[c].z;
                    sc[r][c] += qv[r].w * kv[c].w;
                }
        }

        // ---- Causal mask on diagonal tile ----
        if (kt == qblock) {
            #pragma unroll
            for (int r = 0; r < 4; r++)
                #pragma unroll
                for (int c = 0; c < 4; c++)
                    if (kbase + tx * 4 + c > qbase + ty * 4 + r) sc[r][c] = -1e30f;
        }

        // ---- Store scores to smem ----
        #pragma unroll
        for (int r = 0; r < 4; r++) {
            float4 v = make_float4(sc[r][0], sc[r][1], sc[r][2], sc[r][3]);
            *(float4*)(sS + (ty * 4 + r) * PADS + tx * 4) = v;
        }
        __syncthreads();

        // ---- Online softmax: 4 threads per row, 16 elems each ----
        {
            const int row = tid >> 2;
            const int part = tid & 3;
            float* srow = sS + row * PADS + part * 16;
            float vals[16];
            float mloc = -1e30f;
            #pragma unroll
            for (int e = 0; e < 16; e++) { vals[e] = srow[e]; mloc = fmaxf(mloc, vals[e]); }
            mloc = fmaxf(mloc, __shfl_xor_sync(0xffffffffu, mloc, 1));
            mloc = fmaxf(mloc, __shfl_xor_sync(0xffffffffu, mloc, 2));
            const float mprev = sM[row];
            const float mnew = fmaxf(mprev, mloc);
            float ssum = 0.0f;
            #pragma unroll
            for (int e = 0; e < 16; e++) {
                float p = __expf(vals[e] - mnew);
                ssum += p;
                srow[e] = p;
            }
            ssum += __shfl_xor_sync(0xffffffffu, ssum, 1);
            ssum += __shfl_xor_sync(0xffffffffu, ssum, 2);
            if (part == 0) {
                float f = __expf(mprev - mnew);
                sF[row] = f;
                sM[row] = mnew;
                sL[row] = sL[row] * f + ssum;
            }
        }
        __syncthreads();

        // ---- Rescale accumulators ----
        float fr[4];
        #pragma unroll
        for (int r = 0; r < 4; r++) fr[r] = sF[ty * 4 + r];
        #pragma unroll
        for (int r = 0; r < 4; r++)
            #pragma unroll
            for (int c = 0; c < 8; c++) acc[r][c] *= fr[r];

        // ---- O += P V  (each thread: 4 rows x 8 cols {tx*4..+3, 64+tx*4..+3}) ----
        #pragma unroll 4
        for (int j0 = 0; j0 < BN; j0 += 4) {
            float pr[4][4];
            #pragma unroll
            for (int r = 0; r < 4; r++) {
                float4 p = *(float4*)(sS + (ty * 4 + r) * PADS + j0);
                pr[r][0] = p.x; pr[r][1] = p.y; pr[r][2] = p.z; pr[r][3] = p.w;
            }
            #pragma unroll
            for (int jj = 0; jj < 4; jj++) {
                float4 v0 = *(float4*)(sV + (j0 + jj) * PADR + tx * 4);
                float4 v1 = *(float4*)(sV + (j0 + jj) * PADR + 64 + tx * 4);
                #pragma unroll
                for (int r = 0; r < 4; r++) {
                    float p = pr[r][jj];
                    acc[r][0] += p * v0.x; acc[r][1] += p * v0.y;
                    acc[r][2] += p * v0.z; acc[r][3] += p * v0.w;
                    acc[r][4] += p * v1.x; acc[r][5] += p * v1.y;
                    acc[r][6] += p * v1.z; acc[r][7] += p * v1.w;
                }
            }
        }
    }

    // ---- Epilogue: normalize and write O ----
    // (sL writes happened before the last __syncthreads inside the loop)
    #pragma unroll
    for (int r = 0; r < 4; r++) {
        const int i = ty * 4 + r;
        const float linv = 1.0f / sL[i];
        const long q = qbase + i;
        float* og = O + q * qstride + (long)b * HQ * DH + (long)h * DH;
        float4 o0 = make_float4(acc[r][0] * linv, acc[r][1] * linv,
                                acc[r][2] * linv, acc[r][3] * linv);
        float4 o1 = make_float4(acc[r][4] * linv, acc[r][5] * linv,
                                acc[r][6] * linv, acc[r][7] * linv);
        *(float4*)(og + tx * 4) = o0;
        *(float4*)(og + 64 + tx * 4) = o1;
    }
}

extern "C" void kernel_launch(void* const* d_in, const int* in_sizes, int n_in,
                              void* d_out, int out_size)
{
    const float* Q = (const float*)d_in[0];
    const float* K = (const float*)d_in[1];
    const float* V = (const float*)d_in[2];
    float* O = (float*)d_out;

    const size_t smem_bytes = (size_t)SMEM_FLOATS * sizeof(float);
    cudaFuncSetAttribute(fa_fp32_kernel,
                         cudaFuncAttributeMaxDynamicSharedMemorySize,
                         (int)smem_bytes);

    dim3 grid(S_LEN / BM, HQ, BATCH);   // (32, 32, 2) = 2048 CTAs
    dim3 block(NTHREADS);
    fa_fp32_kernel<<<grid, block, smem_bytes>>>(Q, K, V, O);
}

// round 2
// speedup vs baseline: 10.0528x; 10.0528x over previous
#include <cuda_runtime.h>
#include <cuda_fp16.h>
#include <cstdint>

// Problem constants: S=2048, B=2, HQ=32, HKV=8, D=128
#define S_LEN 2048
#define BATCH 2
#define HQ 32
#define HKV 8
#define DH 128
#define GROUP 4
#define SCALE 0.08838834764831845f  // 1/sqrt(128)

#define BM 64
#define BN 64
#define PITCH 136            // halves per smem row (272B: ldmatrix conflict-free)
#define NTHREADS 128         // 4 warps, each owns 16 query rows

#define QS (BATCH * HQ * DH)   // 8192 floats per seq step (Q/O)
#define KS (BATCH * HKV * DH)  // 2048 floats per seq step (K/V)

#define SMEM_BYTES ((BM + 2 * BN) * PITCH * sizeof(__half))  // 52224

__device__ __forceinline__ uint32_t smem_u32(const void* p) {
    uint32_t a;
    asm("{ .reg .u64 t; cvta.to.shared.u64 t, %1; cvt.u32.u64 %0, t; }"
        : "=r"(a) : "l"(p));
    return a;
}
__device__ __forceinline__ void ldsm_x4(uint32_t& r0, uint32_t& r1, uint32_t& r2,
                                        uint32_t& r3, uint32_t a) {
    asm volatile("ldmatrix.sync.aligned.m8n8.x4.shared.b16 {%0,%1,%2,%3}, [%4];"
                 : "=r"(r0), "=r"(r1), "=r"(r2), "=r"(r3) : "r"(a));
}
__device__ __forceinline__ void ldsm_x2(uint32_t& r0, uint32_t& r1, uint32_t a) {
    asm volatile("ldmatrix.sync.aligned.m8n8.x2.shared.b16 {%0,%1}, [%2];"
                 : "=r"(r0), "=r"(r1) : "r"(a));
}
__device__ __forceinline__ void ldsm_x2t(uint32_t& r0, uint32_t& r1, uint32_t a) {
    asm volatile("ldmatrix.sync.aligned.m8n8.x2.trans.shared.b16 {%0,%1}, [%2];"
                 : "=r"(r0), "=r"(r1) : "r"(a));
}
__device__ __forceinline__ void mma16816(float& c0, float& c1, float& c2, float& c3,
                                         uint32_t a0, uint32_t a1, uint32_t a2,
                                         uint32_t a3, uint32_t b0, uint32_t b1) {
    asm volatile(
        "mma.sync.aligned.m16n8k16.row.col.f32.f16.f16.f32 "
        "{%0,%1,%2,%3}, {%4,%5,%6,%7}, {%8,%9}, {%0,%1,%2,%3};"
        : "+f"(c0), "+f"(c1), "+f"(c2), "+f"(c3)
        : "r"(a0), "r"(a1), "r"(a2), "r"(a3), "r"(b0), "r"(b1));
}
__device__ __forceinline__ uint32_t h2u(__half2 h) {
    return *reinterpret_cast<uint32_t*>(&h);
}

__global__ void __launch_bounds__(NTHREADS, 2)
fa_hmma_kernel(const float* __restrict__ Q, const float* __restrict__ K,
               const float* __restrict__ V, float* __restrict__ O)
{
    extern __shared__ __half sm[];
    __half* sQ = sm;
    __half* sK = sQ + BM * PITCH;
    __half* sV = sK + BN * PITCH;

    const int tid = threadIdx.x;
    const int warp = tid >> 5;
    const int lane = tid & 31;

    const int qblock = (S_LEN / BM - 1) - blockIdx.x;  // heavy blocks first
    const int h = blockIdx.y, b = blockIdx.z;
    const int hk = h / GROUP;
    const int qbase = qblock * BM;

    // ---- Load Q tile: fp32 -> scaled fp16 in smem ----
    {
        const float* qg = Q + (size_t)qbase * QS + (size_t)b * HQ * DH + (size_t)h * DH;
        #pragma unroll
        for (int i = 0; i < 16; i++) {
            int e = tid + i * NTHREADS;
            int r = e >> 5, c4 = e & 31;
            float4 v = *(const float4*)(qg + (size_t)r * QS + c4 * 4);
            *(__half2*)(sQ + r * PITCH + c4 * 4)     = __floats2half2_rn(v.x * SCALE, v.y * SCALE);
            *(__half2*)(sQ + r * PITCH + c4 * 4 + 2) = __floats2half2_rn(v.z * SCALE, v.w * SCALE);
        }
    }

    float acc[16][4];
    #pragma unroll
    for (int n = 0; n < 16; n++)
        #pragma unroll
        for (int c = 0; c < 4; c++) acc[n][c] = 0.0f;
    float m0 = -1e30f, m1 = -1e30f, l0 = 0.0f, l1 = 0.0f;

    const float* kg = K + (size_t)b * HKV * DH + (size_t)hk * DH;
    const float* vg = V + (size_t)b * HKV * DH + (size_t)hk * DH;

    // ldmatrix per-lane base addresses (bytes)
    // A (Q, .x4): row = warp*16 + (lane&15), colHalf = (lane>>4)*8  (+ kk*16)
    const uint32_t aAddr = smem_u32(sQ) +
        (((warp * 16 + (lane & 15)) * PITCH + (lane >> 4) * 8) << 1);
    // B (K, .x2): row = (lane&7) (+ 8j), colHalf = ((lane&15)>>3)*8 (+ kk*16)
    const uint32_t bAddr = smem_u32(sK) +
        ((((lane & 7)) * PITCH + (((lane & 15) >> 3)) * 8) << 1);
    // V (.x2.trans): row = (lane&15) (+ kk*16), colHalf = n*8
    const uint32_t vAddr = smem_u32(sV) + (((lane & 15) * PITCH) << 1);

    for (int kt = 0; kt <= qblock; kt++) {
        __syncthreads();   // previous iteration's readers done with sK/sV
        const int kbase = kt * BN;

        // ---- Load K,V tiles: fp32 -> fp16 smem ----
        #pragma unroll
        for (int i = 0; i < 16; i++) {
            int e = tid + i * NTHREADS;
            int r = e >> 5, c4 = e & 31;
            float4 kv = *(const float4*)(kg + (size_t)(kbase + r) * KS + c4 * 4);
            float4 vv = *(const float4*)(vg + (size_t)(kbase + r) * KS + c4 * 4);
            *(__half2*)(sK + r * PITCH + c4 * 4)     = __floats2half2_rn(kv.x, kv.y);
            *(__half2*)(sK + r * PITCH + c4 * 4 + 2) = __floats2half2_rn(kv.z, kv.w);
            *(__half2*)(sV + r * PITCH + c4 * 4)     = __floats2half2_rn(vv.x, vv.y);
            *(__half2*)(sV + r * PITCH + c4 * 4 + 2) = __floats2half2_rn(vv.z, vv.w);
        }
        __syncthreads();

        // ---- S = Q K^T : 8 k-steps x 8 n-frags per warp ----
        float sc[8][4];
        #pragma unroll
        for (int j = 0; j < 8; j++)
            #pragma unroll
            for (int c = 0; c < 4; c++) sc[j][c] = 0.0f;

        #pragma unroll
        for (int kk = 0; kk < 8; kk++) {
            uint32_t a0, a1, a2, a3;
            ldsm_x4(a0, a1, a2, a3, aAddr + kk * 32);  // 16 halves = 32B
            #pragma unroll
            for (int j = 0; j < 8; j++) {
                uint32_t b0, b1;
                ldsm_x2(b0, b1, bAddr + ((j * 8 * PITCH) << 1) + kk * 32);
                mma16816(sc[j][0], sc[j][1], sc[j][2], sc[j][3],
                         a0, a1, a2, a3, b0, b1);
            }
        }

        // ---- Causal mask (diagonal tile only; kbase == qbase here) ----
        if (kt == qblock) {
            const int row0 = warp * 16 + (lane >> 2);
            const int col0 = (lane & 3) * 2;
            #pragma unroll
            for (int j = 0; j < 8; j++) {
                int c = j * 8 + col0;
                if (c     > row0)     sc[j][0] = -1e30f;
                if (c + 1 > row0)     sc[j][1] = -1e30f;
                if (c     > row0 + 8) sc[j][2] = -1e30f;
                if (c + 1 > row0 + 8) sc[j][3] = -1e30f;
            }
        }

        // ---- Online softmax (registers + 4-lane shfl) ----
        float mt0 = m0, mt1 = m1;
        #pragma unroll
        for (int j = 0; j < 8; j++) {
            mt0 = fmaxf(mt0, fmaxf(sc[j][0], sc[j][1]));
            mt1 = fmaxf(mt1, fmaxf(sc[j][2], sc[j][3]));
        }
        mt0 = fmaxf(mt0, __shfl_xor_sync(0xffffffffu, mt0, 1));
        mt0 = fmaxf(mt0, __shfl_xor_sync(0xffffffffu, mt0, 2));
        mt1 = fmaxf(mt1, __shfl_xor_sync(0xffffffffu, mt1, 1));
        mt1 = fmaxf(mt1, __shfl_xor_sync(0xffffffffu, mt1, 2));

        const float f0 = __expf(m0 - mt0);
        const float f1 = __expf(m1 - mt1);
        m0 = mt0; m1 = mt1;

        float rs0 = 0.0f, rs1 = 0.0f;
        uint32_t ph[8][2];
        #pragma unroll
        for (int j = 0; j < 8; j++) {
            float p0 = __expf(sc[j][0] - m0);
            float p1 = __expf(sc[j][1] - m0);
            float p2 = __expf(sc[j][2] - m1);
            float p3 = __expf(sc[j][3] - m1);
            rs0 += p0 + p1;
            rs1 += p2 + p3;
            ph[j][0] = h2u(__floats2half2_rn(p0, p1));
            ph[j][1] = h2u(__floats2half2_rn(p2, p3));
        }
        l0 = l0 * f0 + rs0;
        l1 = l1 * f1 + rs1;

        #pragma unroll
        for (int n = 0; n < 16; n++) {
            acc[n][0] *= f0; acc[n][1] *= f0;
            acc[n][2] *= f1; acc[n][3] *= f1;
        }

        // ---- O += P V : 4 k-steps x 16 n-frags ----
        #pragma unroll
        for (int kk = 0; kk < 4; kk++) {
            uint32_t a0 = ph[2 * kk][0], a1 = ph[2 * kk][1];
            uint32_t a2 = ph[2 * kk + 1][0], a3 = ph[2 * kk + 1][1];
            #pragma unroll
            for (int n = 0; n < 16; n++) {
                uint32_t b0, b1;
                ldsm_x2t(b0, b1, vAddr + ((kk * 16 * PITCH + n * 8) << 1));
                mma16816(acc[n][0], acc[n][1], acc[n][2], acc[n][3],
                         a0, a1, a2, a3, b0, b1);
            }
        }
    }

    // ---- Epilogue ----
    l0 += __shfl_xor_sync(0xffffffffu, l0, 1);
    l0 += __shfl_xor_sync(0xffffffffu, l0, 2);
    l1 += __shfl_xor_sync(0xffffffffu, l1, 1);
    l1 += __shfl_xor_sync(0xffffffffu, l1, 2);
    const float inv0 = 1.0f / l0;
    const float inv1 = 1.0f / l1;

    const size_t r0 = (size_t)qbase + warp * 16 + (lane >> 2);
    float* og0 = O + r0 * QS + (size_t)b * HQ * DH + (size_t)h * DH + (lane & 3) * 2;
    float* og1 = og0 + (size_t)8 * QS;
    #pragma unroll
    for (int n = 0; n < 16; n++) {
        float2 o0 = make_float2(acc[n][0] * inv0, acc[n][1] * inv0);
        float2 o1 = make_float2(acc[n][2] * inv1, acc[n][3] * inv1);
        *(float2*)(og0 + n * 8) = o0;
        *(float2*)(og1 + n * 8) = o1;
    }
}

extern "C" void kernel_launch(void* const* d_in, const int* in_sizes, int n_in,
                              void* d_out, int out_size)
{
    const float* Q = (const float*)d_in[0];
    const float* K = (const float*)d_in[1];
    const float* V = (const float*)d_in[2];
    float* O = (float*)d_out;

    cudaFuncSetAttribute(fa_hmma_kernel,
                         cudaFuncAttributeMaxDynamicSharedMemorySize,
                         (int)SMEM_BYTES);

    dim3 grid(S_LEN / BM, HQ, BATCH);  // (32, 32, 2) = 2048 CTAs
    fa_hmma_kernel<<<grid, NTHREADS, SMEM_BYTES>>>(Q, K, V, O);
}

// round 3
// speedup vs baseline: 12.1401x; 1.2076x over previous
#include <cuda_runtime.h>
#include <cuda_fp16.h>
#include <cstdint>

// Problem constants: S=2048, B=2, HQ=32, HKV=8, D=128
#define S_LEN 2048
#define BATCH 2
#define HQ 32
#define HKV 8
#define DH 128
#define GROUP 4
#define SCALE 0.08838834764831845f  // 1/sqrt(128)

#define BM 128               // query tile (8 warps x 16 rows)
#define BN 64                // key tile
#define PITCH 136            // halves per smem row (272B; ldmatrix conflict-free)
#define NTHREADS 256

#define QS (BATCH * HQ * DH)   // 8192 floats per seq step (Q/O)
#define KS (BATCH * HKV * DH)  // 2048 elems per seq step (K/V)

#define KV_ELEMS (S_LEN * BATCH * HKV * DH)  // 4194304

// fp16 copies of K and V (converted once per launch by a pre-pass kernel)
__device__ __half g_Kh[KV_ELEMS];
__device__ __half g_Vh[KV_ELEMS];

// smem: K double-buffer then V double-buffer; Q staged in the K region at start
#define STAGE_HALVES (BN * PITCH)
#define SMEM_BYTES (4 * STAGE_HALVES * sizeof(__half))  // 69632

__device__ __forceinline__ uint32_t smem_u32(const void* p) {
    uint32_t a;
    asm("{ .reg .u64 t; cvta.to.shared.u64 t, %1; cvt.u32.u64 %0, t; }"
        : "=r"(a) : "l"(p));
    return a;
}
__device__ __forceinline__ void cp16(uint32_t dst, const void* src) {
    asm volatile("cp.async.cg.shared.global [%0], [%1], 16;" :: "r"(dst), "l"(src));
}
__device__ __forceinline__ void cp_commit() {
    asm volatile("cp.async.commit_group;");
}
__device__ __forceinline__ void cp_wait1() {
    asm volatile("cp.async.wait_group 1;");
}
__device__ __forceinline__ void ldsm_x4(uint32_t& r0, uint32_t& r1, uint32_t& r2,
                                        uint32_t& r3, uint32_t a) {
    asm volatile("ldmatrix.sync.aligned.m8n8.x4.shared.b16 {%0,%1,%2,%3}, [%4];"
                 : "=r"(r0), "=r"(r1), "=r"(r2), "=r"(r3) : "r"(a));
}
__device__ __forceinline__ void ldsm_x2(uint32_t& r0, uint32_t& r1, uint32_t a) {
    asm volatile("ldmatrix.sync.aligned.m8n8.x2.shared.b16 {%0,%1}, [%2];"
                 : "=r"(r0), "=r"(r1) : "r"(a));
}
__device__ __forceinline__ void ldsm_x2t(uint32_t& r0, uint32_t& r1, uint32_t a) {
    asm volatile("ldmatrix.sync.aligned.m8n8.x2.trans.shared.b16 {%0,%1}, [%2];"
                 : "=r"(r0), "=r"(r1) : "r"(a));
}
__device__ __forceinline__ void mma16816(float& c0, float& c1, float& c2, float& c3,
                                         uint32_t a0, uint32_t a1, uint32_t a2,
                                         uint32_t a3, uint32_t b0, uint32_t b1) {
    asm volatile(
        "mma.sync.aligned.m16n8k16.row.col.f32.f16.f16.f32 "
        "{%0,%1,%2,%3}, {%4,%5,%6,%7}, {%8,%9}, {%0,%1,%2,%3};"
        : "+f"(c0), "+f"(c1), "+f"(c2), "+f"(c3)
        : "r"(a0), "r"(a1), "r"(a2), "r"(a3), "r"(b0), "r"(b1));
}
__device__ __forceinline__ uint32_t h2u(__half2 h) {
    return *reinterpret_cast<uint32_t*>(&h);
}

// ---- Pre-pass: fp32 K,V -> fp16 globals ----
__global__ void __launch_bounds__(256)
convert_kv_kernel(const float* __restrict__ K, const float* __restrict__ V)
{
    const size_t i = (size_t)blockIdx.x * 256 + threadIdx.x;  // over KV_ELEMS/4
    float4 k = ((const float4*)K)[i];
    float4 v = ((const float4*)V)[i];
    *(__half2*)(g_Kh + i * 4)     = __floats2half2_rn(k.x, k.y);
    *(__half2*)(g_Kh + i * 4 + 2) = __floats2half2_rn(k.z, k.w);
    *(__half2*)(g_Vh + i * 4)     = __floats2half2_rn(v.x, v.y);
    *(__half2*)(g_Vh + i * 4 + 2) = __floats2half2_rn(v.z, v.w);
}

__global__ void __launch_bounds__(NTHREADS, 1)
fa_hmma2_kernel(const float* __restrict__ Q, float* __restrict__ O)
{
    extern __shared__ __half sm[];
    // layout: [ sK0 | sK1 | sV0 | sV1 ], each STAGE_HALVES
    const uint32_t smBase = smem_u32(sm);

    const int tid = threadIdx.x;
    const int warp = tid >> 5;
    const int lane = tid & 31;

    const int qblock = (S_LEN / BM - 1) - blockIdx.x;  // heavy blocks first
    const int h = blockIdx.y, b = blockIdx.z;
    const int hk = h / GROUP;
    const int qbase = qblock * BM;
    const int NT = 2 * qblock + 2;  // k-tiles of BN covering k <= qbase+127

    const __half* kg = g_Kh + ((size_t)b * HKV + hk) * DH;
    const __half* vg = g_Vh + ((size_t)b * HKV + hk) * DH;

    // ---- Stage Q (fp32 -> scaled fp16) into sK region, ldsm to registers ----
    uint32_t qa[8][4];
    {
        const float* qg = Q + (size_t)qbase * QS + (size_t)b * HQ * DH + (size_t)h * DH;
        #pragma unroll
        for (int i = 0; i < 16; i++) {
            int e = tid + i * NTHREADS;          // 4096 float4 = 128 rows x 32
            int r = e >> 5, c4 = e & 31;
            float4 v = *(const float4*)(qg + (size_t)r * QS + c4 * 4);
            *(__half2*)(sm + r * PITCH + c4 * 4)     = __floats2half2_rn(v.x * SCALE, v.y * SCALE);
            *(__half2*)(sm + r * PITCH + c4 * 4 + 2) = __floats2half2_rn(v.z * SCALE, v.w * SCALE);
        }
        __syncthreads();
        const uint32_t qAddr = smBase +
            (((warp * 16 + (lane & 15)) * PITCH + (lane >> 4) * 8) << 1);
        #pragma unroll
        for (int kk = 0; kk < 8; kk++)
            ldsm_x4(qa[kk][0], qa[kk][1], qa[kk][2], qa[kk][3], qAddr + kk * 32);
        __syncthreads();   // all Q reads done before cp.async overwrites sK
    }

    // ---- cp.async prologue: prefetch tiles 0 and 1 ----
    const uint32_t kStage[2] = { smBase, smBase + (STAGE_HALVES << 1) };
    const uint32_t vStage[2] = { smBase + (2 * STAGE_HALVES << 1),
                                 smBase + (3 * STAGE_HALVES << 1) };
    const int lr = tid >> 4;        // 0..15 base row step (x4 per thread)
    const int lc = tid & 15;        // 16B chunk
    #pragma unroll
    for (int t = 0; t < 2; t++) {
        if (t < NT) {
            const int kbase = t * BN;
            #pragma unroll
            for (int i = 0; i < 4; i++) {
                int r = lr + i * 16;
                uint32_t off = ((r * PITCH + lc * 8) << 1);
                cp16(kStage[t] + off, kg + (size_t)(kbase + r) * KS + lc * 8);
                cp16(vStage[t] + off, vg + (size_t)(kbase + r) * KS + lc * 8);
            }
        }
        cp_commit();
    }

    float acc[16][4];
    #pragma unroll
    for (int n = 0; n < 16; n++)
        #pragma unroll
        for (int c = 0; c < 4; c++) acc[n][c] = 0.0f;
    float m0 = -1e30f, m1 = -1e30f, l0 = 0.0f, l1 = 0.0f;

    for (int kt = 0; kt < NT; kt++) {
        const int stage = kt & 1;
        const int kbase = kt * BN;
        cp_wait1();
        __syncthreads();

        const uint32_t bAddr = kStage[stage] +
            ((((lane & 7)) * PITCH + (((lane & 15) >> 3)) * 8) << 1);
        const uint32_t vAddr = vStage[stage] + (((lane & 15) * PITCH) << 1);

        // ---- S = Q K^T ----
        float sc[8][4];
        #pragma unroll
        for (int j = 0; j < 8; j++)
            #pragma unroll
            for (int c = 0; c < 4; c++) sc[j][c] = 0.0f;

        #pragma unroll
        for (int kk = 0; kk < 8; kk++) {
            #pragma unroll
            for (int j = 0; j < 8; j++) {
                uint32_t b0, b1;
                ldsm_x2(b0, b1, bAddr + ((j * 8 * PITCH) << 1) + kk * 32);
                mma16816(sc[j][0], sc[j][1], sc[j][2], sc[j][3],
                         qa[kk][0], qa[kk][1], qa[kk][2], qa[kk][3], b0, b1);
            }
        }

        // ---- Causal mask (last two k-tiles overlap the diagonal) ----
        if (kt >= 2 * qblock) {
            const int row0 = qbase + warp * 16 + (lane >> 2);
            const int col0 = kbase + (lane & 3) * 2;
            #pragma unroll
            for (int j = 0; j < 8; j++) {
                int c = col0 + j * 8;
                if (c     > row0)     sc[j][0] = -1e30f;
                if (c + 1 > row0)     sc[j][1] = -1e30f;
                if (c     > row0 + 8) sc[j][2] = -1e30f;
                if (c + 1 > row0 + 8) sc[j][3] = -1e30f;
            }
        }

        // ---- Online softmax ----
        float mt0 = m0, mt1 = m1;
        #pragma unroll
        for (int j = 0; j < 8; j++) {
            mt0 = fmaxf(mt0, fmaxf(sc[j][0], sc[j][1]));
            mt1 = fmaxf(mt1, fmaxf(sc[j][2], sc[j][3]));
        }
        mt0 = fmaxf(mt0, __shfl_xor_sync(0xffffffffu, mt0, 1));
        mt0 = fmaxf(mt0, __shfl_xor_sync(0xffffffffu, mt0, 2));
        mt1 = fmaxf(mt1, __shfl_xor_sync(0xffffffffu, mt1, 1));
        mt1 = fmaxf(mt1, __shfl_xor_sync(0xffffffffu, mt1, 2));

        const float f0 = __expf(m0 - mt0);
        const float f1 = __expf(m1 - mt1);
        m0 = mt0; m1 = mt1;

        float rs0 = 0.0f, rs1 = 0.0f;
        uint32_t ph[8][2];
        #pragma unroll
        for (int j = 0; j < 8; j++) {
            float p0 = __expf(sc[j][0] - m0);
            float p1 = __expf(sc[j][1] - m0);
            float p2 = __expf(sc[j][2] - m1);
            float p3 = __expf(sc[j][3] - m1);
            rs0 += p0 + p1;
            rs1 += p2 + p3;
            ph[j][0] = h2u(__floats2half2_rn(p0, p1));
            ph[j][1] = h2u(__floats2half2_rn(p2, p3));
        }
        l0 = l0 * f0 + rs0;
        l1 = l1 * f1 + rs1;

        #pragma unroll
        for (int n = 0; n < 16; n++) {
            acc[n][0] *= f0; acc[n][1] *= f0;
            acc[n][2] *= f1; acc[n][3] *= f1;
        }

        // ---- O += P V ----
        #pragma unroll
        for (int kk = 0; kk < 4; kk++) {
            uint32_t a0 = ph[2 * kk][0], a1 = ph[2 * kk][1];
            uint32_t a2 = ph[2 * kk + 1][0], a3 = ph[2 * kk + 1][1];
            #pragma unroll
            for (int n = 0; n < 16; n++) {
                uint32_t b0, b1;
                ldsm_x2t(b0, b1, vAddr + ((kk * 16 * PITCH + n * 8) << 1));
                mma16816(acc[n][0], acc[n][1], acc[n][2], acc[n][3],
                         a0, a1, a2, a3, b0, b1);
            }
        }

        __syncthreads();   // all warps done with this stage
        // ---- Prefetch tile kt+2 into this stage ----
        if (kt + 2 < NT) {
            const int nb = (kt + 2) * BN;
            #pragma unroll
            for (int i = 0; i < 4; i++) {
                int r = lr + i * 16;
                uint32_t off = ((r * PITCH + lc * 8) << 1);
                cp16(kStage[stage] + off, kg + (size_t)(nb + r) * KS + lc * 8);
                cp16(vStage[stage] + off, vg + (size_t)(nb + r) * KS + lc * 8);
            }
        }
        cp_commit();
    }

    // ---- Epilogue ----
    l0 += __shfl_xor_sync(0xffffffffu, l0, 1);
    l0 += __shfl_xor_sync(0xffffffffu, l0, 2);
    l1 += __shfl_xor_sync(0xffffffffu, l1, 1);
    l1 += __shfl_xor_sync(0xffffffffu, l1, 2);
    const float inv0 = 1.0f / l0;
    const float inv1 = 1.0f / l1;

    const size_t r0 = (size_t)qbase + warp * 16 + (lane >> 2);
    float* og0 = O + r0 * QS + (size_t)b * HQ * DH + (size_t)h * DH + (lane & 3) * 2;
    float* og1 = og0 + (size_t)8 * QS;
    #pragma unroll
    for (int n = 0; n < 16; n++) {
        *(float2*)(og0 + n * 8) = make_float2(acc[n][0] * inv0, acc[n][1] * inv0);
        *(float2*)(og1 + n * 8) = make_float2(acc[n][2] * inv1, acc[n][3] * inv1);
    }
}

extern "C" void kernel_launch(void* const* d_in, const int* in_sizes, int n_in,
                              void* d_out, int out_size)
{
    const float* Q = (const float*)d_in[0];
    const float* K = (const float*)d_in[1];
    const float* V = (const float*)d_in[2];
    float* O = (float*)d_out;

    convert_kv_kernel<<<KV_ELEMS / 4 / 256, 256>>>(K, V);

    cudaFuncSetAttribute(fa_hmma2_kernel,
                         cudaFuncAttributeMaxDynamicSharedMemorySize,
                         (int)SMEM_BYTES);
    dim3 grid(S_LEN / BM, HQ, BATCH);  // (16, 32, 2) = 1024 CTAs
    fa_hmma2_kernel<<<grid, NTHREADS, SMEM_BYTES>>>(Q, O);
}

// round 4
// speedup vs baseline: 12.9877x; 1.0698x over previous
#include <cuda_runtime.h>
#include <cuda_fp16.h>
#include <cstdint>

// Problem constants: S=2048, B=2, HQ=32, HKV=8, D=128
#define S_LEN 2048
#define BATCH 2
#define HQ 32
#define HKV 8
#define DH 128
#define GROUP 4
// 1/sqrt(128) * log2(e)  — logits land in exp2 domain
#define QSCALE 0.1275325340386934f

#define BM 128               // query tile (8 warps x 16 rows)
#define BN 128               // key tile
#define PITCH 136            // halves per smem row (272B; ldmatrix conflict-free)
#define NTHREADS 256

#define QS (BATCH * HQ * DH)   // 8192 floats per seq step (Q/O)
#define KS (BATCH * HKV * DH)  // 2048 elems per seq step (K/V)

#define KV_ELEMS (S_LEN * BATCH * HKV * DH)  // 4194304

__device__ __half g_Kh[KV_ELEMS];
__device__ __half g_Vh[KV_ELEMS];

#define STAGE_HALVES (BN * PITCH)                       // 17408
#define SMEM_BYTES (4 * STAGE_HALVES * sizeof(__half))  // 139264

__device__ __forceinline__ uint32_t smem_u32(const void* p) {
    uint32_t a;
    asm("{ .reg .u64 t; cvta.to.shared.u64 t, %1; cvt.u32.u64 %0, t; }"
        : "=r"(a) : "l"(p));
    return a;
}
__device__ __forceinline__ void cp16(uint32_t dst, const void* src) {
    asm volatile("cp.async.cg.shared.global [%0], [%1], 16;" :: "r"(dst), "l"(src));
}
__device__ __forceinline__ void cp_commit() { asm volatile("cp.async.commit_group;"); }
__device__ __forceinline__ void cp_wait1()  { asm volatile("cp.async.wait_group 1;"); }

__device__ __forceinline__ void ldsm_x4(uint32_t& r0, uint32_t& r1, uint32_t& r2,
                                        uint32_t& r3, uint32_t a) {
    asm volatile("ldmatrix.sync.aligned.m8n8.x4.shared.b16 {%0,%1,%2,%3}, [%4];"
                 : "=r"(r0), "=r"(r1), "=r"(r2), "=r"(r3) : "r"(a));
}
__device__ __forceinline__ void ldsm_x4t(uint32_t& r0, uint32_t& r1, uint32_t& r2,
                                         uint32_t& r3, uint32_t a) {
    asm volatile("ldmatrix.sync.aligned.m8n8.x4.trans.shared.b16 {%0,%1,%2,%3}, [%4];"
                 : "=r"(r0), "=r"(r1), "=r"(r2), "=r"(r3) : "r"(a));
}
__device__ __forceinline__ void mma16816(float& c0, float& c1, float& c2, float& c3,
                                         uint32_t a0, uint32_t a1, uint32_t a2,
                                         uint32_t a3, uint32_t b0, uint32_t b1) {
    asm volatile(
        "mma.sync.aligned.m16n8k16.row.col.f32.f16.f16.f32 "
        "{%0,%1,%2,%3}, {%4,%5,%6,%7}, {%8,%9}, {%0,%1,%2,%3};"
        : "+f"(c0), "+f"(c1), "+f"(c2), "+f"(c3)
        : "r"(a0), "r"(a1), "r"(a2), "r"(a3), "r"(b0), "r"(b1));
}
__device__ __forceinline__ uint32_t h2u(__half2 h) {
    return *reinterpret_cast<uint32_t*>(&h);
}

// ---- Pre-pass: fp32 K,V -> fp16 globals ----
__global__ void __launch_bounds__(256)
convert_kv_kernel(const float* __restrict__ K, const float* __restrict__ V)
{
    const size_t i = (size_t)blockIdx.x * 256 + threadIdx.x;
    float4 k = ((const float4*)K)[i];
    float4 v = ((const float4*)V)[i];
    *(__half2*)(g_Kh + i * 4)     = __floats2half2_rn(k.x, k.y);
    *(__half2*)(g_Kh + i * 4 + 2) = __floats2half2_rn(k.z, k.w);
    *(__half2*)(g_Vh + i * 4)     = __floats2half2_rn(v.x, v.y);
    *(__half2*)(g_Vh + i * 4 + 2) = __floats2half2_rn(v.z, v.w);
}

__global__ void __launch_bounds__(NTHREADS, 1)
fa_hmma3_kernel(const float* __restrict__ Q, float* __restrict__ O)
{
    extern __shared__ __half sm[];
    const uint32_t smBase = smem_u32(sm);

    const int tid = threadIdx.x;
    const int warp = tid >> 5;
    const int lane = tid & 31;

    const int qblock = (S_LEN / BM - 1) - blockIdx.x;  // heavy blocks first
    const int h = blockIdx.y, b = blockIdx.z;
    const int hk = h / GROUP;
    const int qbase = qblock * BM;
    const int NT = qblock + 1;  // 128-wide k-tiles covering k <= qbase+127

    const __half* kg = g_Kh + ((size_t)b * HKV + hk) * DH;
    const __half* vg = g_Vh + ((size_t)b * HKV + hk) * DH;

    // ---- Stage Q (fp32 -> scaled fp16) into stage0 region; ldsm to registers ----
    uint32_t qa[8][4];
    {
        const float* qg = Q + (size_t)qbase * QS + (size_t)b * HQ * DH + (size_t)h * DH;
        #pragma unroll
        for (int i = 0; i < 16; i++) {
            int e = tid + i * NTHREADS;          // 4096 float4 = 128 rows x 32
            int r = e >> 5, c4 = e & 31;
            float4 v = *(const float4*)(qg + (size_t)r * QS + c4 * 4);
            *(__half2*)(sm + r * PITCH + c4 * 4)     = __floats2half2_rn(v.x * QSCALE, v.y * QSCALE);
            *(__half2*)(sm + r * PITCH + c4 * 4 + 2) = __floats2half2_rn(v.z * QSCALE, v.w * QSCALE);
        }
        __syncthreads();
        const uint32_t qAddr = smBase +
            (((warp * 16 + (lane & 15)) * PITCH + (lane >> 4) * 8) << 1);
        #pragma unroll
        for (int kk = 0; kk < 8; kk++)
            ldsm_x4(qa[kk][0], qa[kk][1], qa[kk][2], qa[kk][3], qAddr + kk * 32);
        __syncthreads();   // Q reads done before cp.async overwrites stage0
    }

    const uint32_t kStage[2] = { smBase, smBase + (uint32_t)(STAGE_HALVES << 1) };
    const uint32_t vStage[2] = { smBase + (uint32_t)(2 * STAGE_HALVES << 1),
                                 smBase + (uint32_t)(3 * STAGE_HALVES << 1) };
    const int lr = tid >> 4;   // 0..15
    const int lc = tid & 15;   // 16B chunk index

    // prologue: prefetch tiles 0 and 1
    #pragma unroll
    for (int t = 0; t < 2; t++) {
        if (t < NT) {
            const int kbase = t * BN;
            #pragma unroll
            for (int i = 0; i < 8; i++) {
                int r = lr + i * 16;
                uint32_t off = (uint32_t)((r * PITCH + lc * 8) << 1);
                cp16(kStage[t] + off, kg + (size_t)(kbase + r) * KS + lc * 8);
                cp16(vStage[t] + off, vg + (size_t)(kbase + r) * KS + lc * 8);
            }
        }
        cp_commit();
    }

    // per-lane ldmatrix bases (add stage base at use)
    // K (.x4, two j per fetch): row = jp*16 + (lane&7) + (lane>>4)*8, colH = kk*16 + ((lane&15)>>3)*8
    const uint32_t kOff = (uint32_t)(
        (((lane & 7) + ((lane >> 4) << 3)) * PITCH + (((lane & 15) >> 3) << 3)) << 1);
    // V (.x4.trans, two n per fetch): row = kk*16 + (lane&15), colH = np*16 + (lane>>4)*8
    const uint32_t vOff = (uint32_t)(
        (((lane & 15)) * PITCH + ((lane >> 4) << 3)) << 1);

    float acc[16][4];
    #pragma unroll
    for (int n = 0; n < 16; n++)
        #pragma unroll
        for (int c = 0; c < 4; c++) acc[n][c] = 0.0f;
    float m0 = -1e30f, m1 = -1e30f, l0 = 0.0f, l1 = 0.0f;

    for (int kt = 0; kt < NT; kt++) {
        const int stage = kt & 1;
        cp_wait1();
        __syncthreads();

        const uint32_t kA = kStage[stage] + kOff;
        const uint32_t vA = vStage[stage] + vOff;

        // ---- S = Q K^T : 8 k-steps x 8 j-pairs ----
        float sc[16][4];
        #pragma unroll
        for (int j = 0; j < 16; j++)
            #pragma unroll
            for (int c = 0; c < 4; c++) sc[j][c] = 0.0f;

        #pragma unroll
        for (int kk = 0; kk < 8; kk++) {
            #pragma unroll
            for (int jp = 0; jp < 8; jp++) {
                uint32_t b0, b1, b2, b3;
                ldsm_x4(b0, b1, b2, b3, kA + (uint32_t)((jp * 16 * PITCH) << 1) + kk * 32);
                mma16816(sc[2*jp][0], sc[2*jp][1], sc[2*jp][2], sc[2*jp][3],
                         qa[kk][0], qa[kk][1], qa[kk][2], qa[kk][3], b0, b1);
                mma16816(sc[2*jp+1][0], sc[2*jp+1][1], sc[2*jp+1][2], sc[2*jp+1][3],
                         qa[kk][0], qa[kk][1], qa[kk][2], qa[kk][3], b2, b3);
            }
        }

        // ---- Causal mask (diagonal tile: kbase == qbase) ----
        if (kt == qblock) {
            const int row0 = warp * 16 + (lane >> 2);
            const int col0 = (lane & 3) * 2;
            #pragma unroll
            for (int j = 0; j < 16; j++) {
                int c = col0 + j * 8;
                if (c     > row0)     sc[j][0] = -1e30f;
                if (c + 1 > row0)     sc[j][1] = -1e30f;
                if (c     > row0 + 8) sc[j][2] = -1e30f;
                if (c + 1 > row0 + 8) sc[j][3] = -1e30f;
            }
        }

        // ---- Online softmax (exp2 domain) ----
        float mt0 = m0, mt1 = m1;
        #pragma unroll
        for (int j = 0; j < 16; j++) {
            mt0 = fmaxf(mt0, fmaxf(sc[j][0], sc[j][1]));
            mt1 = fmaxf(mt1, fmaxf(sc[j][2], sc[j][3]));
        }
        mt0 = fmaxf(mt0, __shfl_xor_sync(0xffffffffu, mt0, 1));
        mt0 = fmaxf(mt0, __shfl_xor_sync(0xffffffffu, mt0, 2));
        mt1 = fmaxf(mt1, __shfl_xor_sync(0xffffffffu, mt1, 1));
        mt1 = fmaxf(mt1, __shfl_xor_sync(0xffffffffu, mt1, 2));

        const float f0 = exp2f(m0 - mt0);
        const float f1 = exp2f(m1 - mt1);
        m0 = mt0; m1 = mt1;

        float rs0 = 0.0f, rs1 = 0.0f;
        uint32_t ph[16][2];
        #pragma unroll
        for (int j = 0; j < 16; j++) {
            float p0 = exp2f(sc[j][0] - m0);
            float p1 = exp2f(sc[j][1] - m0);
            float p2 = exp2f(sc[j][2] - m1);
            float p3 = exp2f(sc[j][3] - m1);
            rs0 += p0 + p1;
            rs1 += p2 + p3;
            ph[j][0] = h2u(__floats2half2_rn(p0, p1));
            ph[j][1] = h2u(__floats2half2_rn(p2, p3));
        }
        l0 = l0 * f0 + rs0;
        l1 = l1 * f1 + rs1;

        #pragma unroll
        for (int n = 0; n < 16; n++) {
            acc[n][0] *= f0; acc[n][1] *= f0;
            acc[n][2] *= f1; acc[n][3] *= f1;
        }

        // ---- O += P V : 8 k-steps x 8 n-pairs ----
        #pragma unroll
        for (int kk = 0; kk < 8; kk++) {
            const uint32_t a0 = ph[2*kk][0], a1 = ph[2*kk][1];
            const uint32_t a2 = ph[2*kk+1][0], a3 = ph[2*kk+1][1];
            #pragma unroll
            for (int np = 0; np < 8; np++) {
                uint32_t b0, b1, b2, b3;
                ldsm_x4t(b0, b1, b2, b3,
                         vA + (uint32_t)(((kk * 16 * PITCH) + np * 16) << 1));
                mma16816(acc[2*np][0], acc[2*np][1], acc[2*np][2], acc[2*np][3],
                         a0, a1, a2, a3, b0, b1);
                mma16816(acc[2*np+1][0], acc[2*np+1][1], acc[2*np+1][2], acc[2*np+1][3],
                         a0, a1, a2, a3, b2, b3);
            }
        }

        __syncthreads();
        // ---- Prefetch tile kt+2 into this stage ----
        if (kt + 2 < NT) {
            const int nb = (kt + 2) * BN;
            #pragma unroll
            for (int i = 0; i < 8; i++) {
                int r = lr + i * 16;
                uint32_t off = (uint32_t)((r * PITCH + lc * 8) << 1);
                cp16(kStage[stage] + off, kg + (size_t)(nb + r) * KS + lc * 8);
                cp16(vStage[stage] + off, vg + (size_t)(nb + r) * KS + lc * 8);
            }
        }
        cp_commit();
    }

    // ---- Epilogue ----
    l0 += __shfl_xor_sync(0xffffffffu, l0, 1);
    l0 += __shfl_xor_sync(0xffffffffu, l0, 2);
    l1 += __shfl_xor_sync(0xffffffffu, l1, 1);
    l1 += __shfl_xor_sync(0xffffffffu, l1, 2);
    const float inv0 = 1.0f / l0;
    const float inv1 = 1.0f / l1;

    const size_t r0 = (size_t)qbase + warp * 16 + (lane >> 2);
    float* og0 = O + r0 * QS + (size_t)b * HQ * DH + (size_t)h * DH + (lane & 3) * 2;
    float* og1 = og0 + (size_t)8 * QS;
    #pragma unroll
    for (int n = 0; n < 16; n++) {
        *(float2*)(og0 + n * 8) = make_float2(acc[n][0] * inv0, acc[n][1] * inv0);
        *(float2*)(og1 + n * 8) = make_float2(acc[n][2] * inv1, acc[n][3] * inv1);
    }
}

extern "C" void kernel_launch(void* const* d_in, const int* in_sizes, int n_in,
                              void* d_out, int out_size)
{
    const float* Q = (const float*)d_in[0];
    const float* K = (const float*)d_in[1];
    const float* V = (const float*)d_in[2];
    float* O = (float*)d_out;

    convert_kv_kernel<<<KV_ELEMS / 4 / 256, 256>>>(K, V);

    cudaFuncSetAttribute(fa_hmma3_kernel,
                         cudaFuncAttributeMaxDynamicSharedMemorySize,
                         (int)SMEM_BYTES);
    dim3 grid(S_LEN / BM, HQ, BATCH);  // (16, 32, 2) = 1024 CTAs
    fa_hmma3_kernel<<<grid, NTHREADS, SMEM_BYTES>>>(Q, O);
}

// round 5
// speedup vs baseline: 13.0176x; 1.0023x over previous
#include <cuda_runtime.h>
#include <cuda_fp16.h>
#include <cstdint>

// Problem constants: S=2048, B=2, HQ=32, HKV=8, D=128
#define S_LEN 2048
#define BATCH 2
#define HQ 32
#define HKV 8
#define DH 128
#define GROUP 4
// 1/sqrt(128) * log2(e)  — logits land in exp2 domain
#define QSCALE 0.1275325340386934f

#define BM 128               // query tile (8 warps x 16 rows)
#define BN 128               // key tile
#define PITCH 136            // halves per smem row (272B; ldmatrix conflict-free)
#define NTHREADS 256

#define QS (BATCH * HQ * DH)   // 8192 floats per seq step (Q/O)
#define KS (BATCH * HKV * DH)  // 2048 elems per seq step (K/V)

#define KV_ELEMS (S_LEN * BATCH * HKV * DH)  // 4194304

__device__ __half g_Kh[KV_ELEMS];
__device__ __half g_Vh[KV_ELEMS];

#define STAGE_HALVES (BN * PITCH)                       // 17408
#define SMEM_BYTES (4 * STAGE_HALVES * sizeof(__half))  // 139264

__device__ __forceinline__ uint32_t smem_u32(const void* p) {
    uint32_t a;
    asm("{ .reg .u64 t; cvta.to.shared.u64 t, %1; cvt.u32.u64 %0, t; }"
        : "=r"(a) : "l"(p));
    return a;
}
__device__ __forceinline__ void cp16(uint32_t dst, const void* src) {
    asm volatile("cp.async.cg.shared.global [%0], [%1], 16;" :: "r"(dst), "l"(src));
}
__device__ __forceinline__ void cp_commit() { asm volatile("cp.async.commit_group;"); }
__device__ __forceinline__ void cp_wait1()  { asm volatile("cp.async.wait_group 1;"); }

__device__ __forceinline__ void ldsm_x4(uint32_t& r0, uint32_t& r1, uint32_t& r2,
                                        uint32_t& r3, uint32_t a) {
    asm volatile("ldmatrix.sync.aligned.m8n8.x4.shared.b16 {%0,%1,%2,%3}, [%4];"
                 : "=r"(r0), "=r"(r1), "=r"(r2), "=r"(r3) : "r"(a));
}
__device__ __forceinline__ void ldsm_x4t(uint32_t& r0, uint32_t& r1, uint32_t& r2,
                                         uint32_t& r3, uint32_t a) {
    asm volatile("ldmatrix.sync.aligned.m8n8.x4.trans.shared.b16 {%0,%1,%2,%3}, [%4];"
                 : "=r"(r0), "=r"(r1), "=r"(r2), "=r"(r3) : "r"(a));
}
__device__ __forceinline__ void mma16816(float& c0, float& c1, float& c2, float& c3,
                                         uint32_t a0, uint32_t a1, uint32_t a2,
                                         uint32_t a3, uint32_t b0, uint32_t b1) {
    asm volatile(
        "mma.sync.aligned.m16n8k16.row.col.f32.f16.f16.f32 "
        "{%0,%1,%2,%3}, {%4,%5,%6,%7}, {%8,%9}, {%0,%1,%2,%3};"
        : "+f"(c0), "+f"(c1), "+f"(c2), "+f"(c3)
        : "r"(a0), "r"(a1), "r"(a2), "r"(a3), "r"(b0), "r"(b1));
}
__device__ __forceinline__ uint32_t h2u(__half2 h) {
    return *reinterpret_cast<uint32_t*>(&h);
}

// ---- Pre-pass: fp32 K,V -> fp16 globals ----
__global__ void __launch_bounds__(256)
convert_kv_kernel(const float* __restrict__ K, const float* __restrict__ V)
{
    const size_t i = (size_t)blockIdx.x * 256 + threadIdx.x;
    float4 k = ((const float4*)K)[i];
    float4 v = ((const float4*)V)[i];
    *(__half2*)(g_Kh + i * 4)     = __floats2half2_rn(k.x, k.y);
    *(__half2*)(g_Kh + i * 4 + 2) = __floats2half2_rn(k.z, k.w);
    *(__half2*)(g_Vh + i * 4)     = __floats2half2_rn(v.x, v.y);
    *(__half2*)(g_Vh + i * 4 + 2) = __floats2half2_rn(v.z, v.w);
}

__global__ void __launch_bounds__(NTHREADS, 1)
fa_hmma3_kernel(const float* __restrict__ Q, float* __restrict__ O)
{
    extern __shared__ __half sm[];
    const uint32_t smBase = smem_u32(sm);

    const int tid = threadIdx.x;
    const int warp = tid >> 5;
    const int lane = tid & 31;

    const int qblock = (S_LEN / BM - 1) - blockIdx.x;  // heavy blocks first
    const int h = blockIdx.y, b = blockIdx.z;
    const int hk = h / GROUP;
    const int qbase = qblock * BM;
    const int NT = qblock + 1;  // 128-wide k-tiles covering k <= qbase+127

    const __half* kg = g_Kh + ((size_t)b * HKV + hk) * DH;
    const __half* vg = g_Vh + ((size_t)b * HKV + hk) * DH;

    // ---- Stage Q (fp32 -> scaled fp16) into stage0 region; ldsm to registers ----
    uint32_t qa[8][4];
    {
        const float* qg = Q + (size_t)qbase * QS + (size_t)b * HQ * DH + (size_t)h * DH;
        #pragma unroll
        for (int i = 0; i < 16; i++) {
            int e = tid + i * NTHREADS;          // 4096 float4 = 128 rows x 32
            int r = e >> 5, c4 = e & 31;
            float4 v = *(const float4*)(qg + (size_t)r * QS + c4 * 4);
            *(__half2*)(sm + r * PITCH + c4 * 4)     = __floats2half2_rn(v.x * QSCALE, v.y * QSCALE);
            *(__half2*)(sm + r * PITCH + c4 * 4 + 2) = __floats2half2_rn(v.z * QSCALE, v.w * QSCALE);
        }
        __syncthreads();
        const uint32_t qAddr = smBase +
            (((warp * 16 + (lane & 15)) * PITCH + (lane >> 4) * 8) << 1);
        #pragma unroll
        for (int kk = 0; kk < 8; kk++)
            ldsm_x4(qa[kk][0], qa[kk][1], qa[kk][2], qa[kk][3], qAddr + kk * 32);
        __syncthreads();   // Q reads done before cp.async overwrites stage0
    }

    const uint32_t kStage[2] = { smBase, smBase + (uint32_t)(STAGE_HALVES << 1) };
    const uint32_t vStage[2] = { smBase + (uint32_t)(2 * STAGE_HALVES << 1),
                                 smBase + (uint32_t)(3 * STAGE_HALVES << 1) };
    const int lr = tid >> 4;   // 0..15
    const int lc = tid & 15;   // 16B chunk index

    // prologue: prefetch tiles 0 and 1
    #pragma unroll
    for (int t = 0; t < 2; t++) {
        if (t < NT) {
            const int kbase = t * BN;
            #pragma unroll
            for (int i = 0; i < 8; i++) {
                int r = lr + i * 16;
                uint32_t off = (uint32_t)((r * PITCH + lc * 8) << 1);
                cp16(kStage[t] + off, kg + (size_t)(kbase + r) * KS + lc * 8);
                cp16(vStage[t] + off, vg + (size_t)(kbase + r) * KS + lc * 8);
            }
        }
        cp_commit();
    }

    // per-lane ldmatrix bases (add stage base at use)
    // K (.x4, two j per fetch): row = jp*16 + (lane&7) + (lane>>4)*8, colH = kk*16 + ((lane&15)>>3)*8
    const uint32_t kOff = (uint32_t)(
        (((lane & 7) + ((lane >> 4) << 3)) * PITCH + (((lane & 15) >> 3) << 3)) << 1);
    // V (.x4.trans, two n per fetch): row = kk*16 + (lane&15), colH = np*16 + (lane>>4)*8
    const uint32_t vOff = (uint32_t)(
        (((lane & 15)) * PITCH + ((lane >> 4) << 3)) << 1);

    float acc[16][4];
    #pragma unroll
    for (int n = 0; n < 16; n++)
        #pragma unroll
        for (int c = 0; c < 4; c++) acc[n][c] = 0.0f;
    float m0 = -1e30f, m1 = -1e30f, l0 = 0.0f, l1 = 0.0f;

    for (int kt = 0; kt < NT; kt++) {
        const int stage = kt & 1;
        cp_wait1();
        __syncthreads();

        const uint32_t kA = kStage[stage] + kOff;
        const uint32_t vA = vStage[stage] + vOff;

        // ---- S = Q K^T : 8 k-steps x 8 j-pairs ----
        float sc[16][4];
        #pragma unroll
        for (int j = 0; j < 16; j++)
            #pragma unroll
            for (int c = 0; c < 4; c++) sc[j][c] = 0.0f;

        #pragma unroll
        for (int kk = 0; kk < 8; kk++) {
            #pragma unroll
            for (int jp = 0; jp < 8; jp++) {
                uint32_t b0, b1, b2, b3;
                ldsm_x4(b0, b1, b2, b3, kA + (uint32_t)((jp * 16 * PITCH) << 1) + kk * 32);
                mma16816(sc[2*jp][0], sc[2*jp][1], sc[2*jp][2], sc[2*jp][3],
                         qa[kk][0], qa[kk][1], qa[kk][2], qa[kk][3], b0, b1);
                mma16816(sc[2*jp+1][0], sc[2*jp+1][1], sc[2*jp+1][2], sc[2*jp+1][3],
                         qa[kk][0], qa[kk][1], qa[kk][2], qa[kk][3], b2, b3);
            }
        }

        // ---- Causal mask (diagonal tile: kbase == qbase) ----
        if (kt == qblock) {
            const int row0 = warp * 16 + (lane >> 2);
            const int col0 = (lane & 3) * 2;
            #pragma unroll
            for (int j = 0; j < 16; j++) {
                int c = col0 + j * 8;
                if (c     > row0)     sc[j][0] = -1e30f;
                if (c + 1 > row0)     sc[j][1] = -1e30f;
                if (c     > row0 + 8) sc[j][2] = -1e30f;
                if (c + 1 > row0 + 8) sc[j][3] = -1e30f;
            }
        }

        // ---- Online softmax (exp2 domain) ----
        float mt0 = m0, mt1 = m1;
        #pragma unroll
        for (int j = 0; j < 16; j++) {
            mt0 = fmaxf(mt0, fmaxf(sc[j][0], sc[j][1]));
            mt1 = fmaxf(mt1, fmaxf(sc[j][2], sc[j][3]));
        }
        mt0 = fmaxf(mt0, __shfl_xor_sync(0xffffffffu, mt0, 1));
        mt0 = fmaxf(mt0, __shfl_xor_sync(0xffffffffu, mt0, 2));
        mt1 = fmaxf(mt1, __shfl_xor_sync(0xffffffffu, mt1, 1));
        mt1 = fmaxf(mt1, __shfl_xor_sync(0xffffffffu, mt1, 2));

        const float f0 = exp2f(m0 - mt0);
        const float f1 = exp2f(m1 - mt1);
        m0 = mt0; m1 = mt1;

        float rs0 = 0.0f, rs1 = 0.0f;
        uint32_t ph[16][2];
        #pragma unroll
        for (int j = 0; j < 16; j++) {
            float p0 = exp2f(sc[j][0] - m0);
            float p1 = exp2f(sc[j][1] - m0);
            float p2 = exp2f(sc[j][2] - m1);
            float p3 = exp2f(sc[j][3] - m1);
            rs0 += p0 + p1;
            rs1 += p2 + p3;
            ph[j][0] = h2u(__floats2half2_rn(p0, p1));
            ph[j][1] = h2u(__floats2half2_rn(p2, p3));
        }
        l0 = l0 * f0 + rs0;
        l1 = l1 * f1 + rs1;

        #pragma unroll
        for (int n = 0; n < 16; n++) {
            acc[n][0] *= f0; acc[n][1] *= f0;
            acc[n][2] *= f1; acc[n][3] *= f1;
        }

        // ---- O += P V : 8 k-steps x 8 n-pairs ----
        #pragma unroll
        for (int kk = 0; kk < 8; kk++) {
            const uint32_t a0 = ph[2*kk][0], a1 = ph[2*kk][1];
            const uint32_t a2 = ph[2*kk+1][0], a3 = ph[2*kk+1][1];
            #pragma unroll
            for (int np = 0; np < 8; np++) {
                uint32_t b0, b1, b2, b3;
                ldsm_x4t(b0, b1, b2, b3,
                         vA + (uint32_t)(((kk * 16 * PITCH) + np * 16) << 1));
                mma16816(acc[2*np][0], acc[2*np][1], acc[2*np][2], acc[2*np][3],
                         a0, a1, a2, a3, b0, b1);
                mma16816(acc[2*np+1][0], acc[2*np+1][1], acc[2*np+1][2], acc[2*np+1][3],
                         a0, a1, a2, a3, b2, b3);
            }
        }

        __syncthreads();
        // ---- Prefetch tile kt+2 into this stage ----
        if (kt + 2 < NT) {
            const int nb = (kt + 2) * BN;
            #pragma unroll
            for (int i = 0; i < 8; i++) {
                int r = lr + i * 16;
                uint32_t off = (uint32_t)((r * PITCH + lc * 8) << 1);
                cp16(kStage[stage] + off, kg + (size_t)(nb + r) * KS + lc * 8);
                cp16(vStage[stage] + off, vg + (size_t)(nb + r) * KS + lc * 8);
            }
        }
        cp_commit();
    }

    // ---- Epilogue ----
    l0 += __shfl_xor_sync(0xffffffffu, l0, 1);
    l0 += __shfl_xor_sync(0xffffffffu, l0, 2);
    l1 += __shfl_xor_sync(0xffffffffu, l1, 1);
    l1 += __shfl_xor_sync(0xffffffffu, l1, 2);
    const float inv0 = 1.0f / l0;
    const float inv1 = 1.0f / l1;

    const size_t r0 = (size_t)qbase + warp * 16 + (lane >> 2);
    float* og0 = O + r0 * QS + (size_t)b * HQ * DH + (size_t)h * DH + (lane & 3) * 2;
    float* og1 = og0 + (size_t)8 * QS;
    #pragma unroll
    for (int n = 0; n < 16; n++) {
        *(float2*)(og0 + n * 8) = make_float2(acc[n][0] * inv0, acc[n][1] * inv0);
        *(float2*)(og1 + n * 8) = make_float2(acc[n][2] * inv1, acc[n][3] * inv1);
    }
}

extern "C" void kernel_launch(void* const* d_in, const int* in_sizes, int n_in,
                              void* d_out, int out_size)
{
    const float* Q = (const float*)d_in[0];
    const float* K = (const float*)d_in[1];
    const float* V = (const float*)d_in[2];
    float* O = (float*)d_out;

    convert_kv_kernel<<<KV_ELEMS / 4 / 256, 256>>>(K, V);

    cudaFuncSetAttribute(fa_hmma3_kernel,
                         cudaFuncAttributeMaxDynamicSharedMemorySize,
                         (int)SMEM_BYTES);
    dim3 grid(S_LEN / BM, HQ, BATCH);  // (16, 32, 2) = 1024 CTAs
    fa_hmma3_kernel<<<grid, NTHREADS, SMEM_BYTES>>>(Q, O);
}

// round 6
// speedup vs baseline: 13.0873x; 1.0054x over previous
#include <cuda_runtime.h>
#include <cuda_fp16.h>
#include <cstdint>

// Problem constants: S=2048, B=2, HQ=32, HKV=8, D=128
#define S_LEN 2048
#define BATCH 2
#define HQ 32
#define HKV 8
#define DH 128
#define GROUP 4
// 1/sqrt(128) * log2(e)  — logits land in exp2 domain
#define QSCALE 0.1275325340386934f

#define BM 128               // query tile (8 warps x 16 rows)
#define BN 128               // key tile (processed as two 64-col halves)
#define PITCH 136            // halves per smem row (272B; ldmatrix conflict-free)
#define NTHREADS 256

#define QS (BATCH * HQ * DH)   // 8192 floats per seq step (Q/O)
#define KS (BATCH * HKV * DH)  // 2048 elems per seq step (K/V)

#define KV_ELEMS (S_LEN * BATCH * HKV * DH)  // 4194304

__device__ __half g_Kh[KV_ELEMS];
__device__ __half g_Vh[KV_ELEMS];

#define STAGE_HALVES (BN * PITCH)                       // 17408
#define SMEM_BYTES (4 * STAGE_HALVES * sizeof(__half))  // 139264

#define ONES2 0x3C003C00u    // half2(1.0, 1.0)

__device__ __forceinline__ uint32_t smem_u32(const void* p) {
    uint32_t a;
    asm("{ .reg .u64 t; cvta.to.shared.u64 t, %1; cvt.u32.u64 %0, t; }"
        : "=r"(a) : "l"(p));
    return a;
}
__device__ __forceinline__ void cp16(uint32_t dst, const void* src) {
    asm volatile("cp.async.cg.shared.global [%0], [%1], 16;" :: "r"(dst), "l"(src));
}
__device__ __forceinline__ void cp_commit() { asm volatile("cp.async.commit_group;"); }
__device__ __forceinline__ void cp_wait1()  { asm volatile("cp.async.wait_group 1;"); }

__device__ __forceinline__ void ldsm_x4(uint32_t& r0, uint32_t& r1, uint32_t& r2,
                                        uint32_t& r3, uint32_t a) {
    asm volatile("ldmatrix.sync.aligned.m8n8.x4.shared.b16 {%0,%1,%2,%3}, [%4];"
                 : "=r"(r0), "=r"(r1), "=r"(r2), "=r"(r3) : "r"(a));
}
__device__ __forceinline__ void ldsm_x4t(uint32_t& r0, uint32_t& r1, uint32_t& r2,
                                         uint32_t& r3, uint32_t a) {
    asm volatile("ldmatrix.sync.aligned.m8n8.x4.trans.shared.b16 {%0,%1,%2,%3}, [%4];"
                 : "=r"(r0), "=r"(r1), "=r"(r2), "=r"(r3) : "r"(a));
}
__device__ __forceinline__ void mma16816(float& c0, float& c1, float& c2, float& c3,
                                         uint32_t a0, uint32_t a1, uint32_t a2,
                                         uint32_t a3, uint32_t b0, uint32_t b1) {
    asm volatile(
        "mma.sync.aligned.m16n8k16.row.col.f32.f16.f16.f32 "
        "{%0,%1,%2,%3}, {%4,%5,%6,%7}, {%8,%9}, {%0,%1,%2,%3};"
        : "+f"(c0), "+f"(c1), "+f"(c2), "+f"(c3)
        : "r"(a0), "r"(a1), "r"(a2), "r"(a3), "r"(b0), "r"(b1));
}
__device__ __forceinline__ uint32_t h2u(__half2 h) {
    return *reinterpret_cast<uint32_t*>(&h);
}
__device__ __forceinline__ uint32_t ex2h2(uint32_t x) {
    uint32_t r;
    asm("ex2.approx.f16x2 %0, %1;" : "=r"(r) : "r"(x));
    return r;
}

// ---- Pre-pass: fp32 K,V -> fp16 globals ----
__global__ void __launch_bounds__(256)
convert_kv_kernel(const float* __restrict__ K, const float* __restrict__ V)
{
    const size_t i = (size_t)blockIdx.x * 256 + threadIdx.x;
    float4 k = ((const float4*)K)[i];
    float4 v = ((const float4*)V)[i];
    *(__half2*)(g_Kh + i * 4)     = __floats2half2_rn(k.x, k.y);
    *(__half2*)(g_Kh + i * 4 + 2) = __floats2half2_rn(k.z, k.w);
    *(__half2*)(g_Vh + i * 4)     = __floats2half2_rn(v.x, v.y);
    *(__half2*)(g_Vh + i * 4 + 2) = __floats2half2_rn(v.z, v.w);
}

__global__ void __launch_bounds__(NTHREADS, 1)
fa_hmma4_kernel(const float* __restrict__ Q, float* __restrict__ O)
{
    extern __shared__ __half sm[];
    const uint32_t smBase = smem_u32(sm);

    const int tid = threadIdx.x;
    const int warp = tid >> 5;
    const int lane = tid & 31;

    const int qblock = (S_LEN / BM - 1) - blockIdx.x;  // heavy blocks first
    const int h = blockIdx.y, b = blockIdx.z;
    const int hk = h / GROUP;
    const int qbase = qblock * BM;
    const int NT = qblock + 1;

    const __half* kg = g_Kh + ((size_t)b * HKV + hk) * DH;
    const __half* vg = g_Vh + ((size_t)b * HKV + hk) * DH;

    // ---- Stage Q (fp32 -> scaled fp16) into stage0; ldsm to registers ----
    uint32_t qa[8][4];
    {
        const float* qg = Q + (size_t)qbase * QS + (size_t)b * HQ * DH + (size_t)h * DH;
        #pragma unroll
        for (int i = 0; i < 16; i++) {
            int e = tid + i * NTHREADS;
            int r = e >> 5, c4 = e & 31;
            float4 v = *(const float4*)(qg + (size_t)r * QS + c4 * 4);
            *(__half2*)(sm + r * PITCH + c4 * 4)     = __floats2half2_rn(v.x * QSCALE, v.y * QSCALE);
            *(__half2*)(sm + r * PITCH + c4 * 4 + 2) = __floats2half2_rn(v.z * QSCALE, v.w * QSCALE);
        }
        __syncthreads();
        const uint32_t qAddr = smBase +
            (((warp * 16 + (lane & 15)) * PITCH + (lane >> 4) * 8) << 1);
        #pragma unroll
        for (int kk = 0; kk < 8; kk++)
            ldsm_x4(qa[kk][0], qa[kk][1], qa[kk][2], qa[kk][3], qAddr + kk * 32);
        __syncthreads();
    }

    const uint32_t kStage[2] = { smBase, smBase + (uint32_t)(STAGE_HALVES << 1) };
    const uint32_t vStage[2] = { smBase + (uint32_t)(2 * STAGE_HALVES << 1),
                                 smBase + (uint32_t)(3 * STAGE_HALVES << 1) };
    const int lr = tid >> 4;
    const int lc = tid & 15;

    #pragma unroll
    for (int t = 0; t < 2; t++) {
        if (t < NT) {
            const int kbase = t * BN;
            #pragma unroll
            for (int i = 0; i < 8; i++) {
                int r = lr + i * 16;
                uint32_t off = (uint32_t)((r * PITCH + lc * 8) << 1);
                cp16(kStage[t] + off, kg + (size_t)(kbase + r) * KS + lc * 8);
                cp16(vStage[t] + off, vg + (size_t)(kbase + r) * KS + lc * 8);
            }
        }
        cp_commit();
    }

    const uint32_t kOff = (uint32_t)(
        (((lane & 7) + ((lane >> 4) << 3)) * PITCH + (((lane & 15) >> 3) << 3)) << 1);
    const uint32_t vOff = (uint32_t)(
        (((lane & 15)) * PITCH + ((lane >> 4) << 3)) << 1);

    float acc[16][4];
    #pragma unroll
    for (int n = 0; n < 16; n++)
        #pragma unroll
        for (int c = 0; c < 4; c++) acc[n][c] = 0.0f;
    float m0 = -1e30f, m1 = -1e30f, l0 = 0.0f, l1 = 0.0f;

    const int mrow0 = warp * 16 + (lane >> 2);
    const int mcol0 = (lane & 3) * 2;

    for (int kt = 0; kt < NT; kt++) {
        const int stage = kt & 1;
        cp_wait1();
        __syncthreads();

        const uint32_t kA = kStage[stage] + kOff;
        const uint32_t vA = vStage[stage] + vOff;
        const bool diag = (kt == qblock);

        // ================= Phase A: S0 = Q K[cols 0:64]^T =================
        float sc0[8][4];
        #pragma unroll
        for (int j = 0; j < 8; j++)
            #pragma unroll
            for (int c = 0; c < 4; c++) sc0[j][c] = 0.0f;
        #pragma unroll
        for (int kk = 0; kk < 8; kk++) {
            #pragma unroll
            for (int jp = 0; jp < 4; jp++) {
                uint32_t b0, b1, b2, b3;
                ldsm_x4(b0, b1, b2, b3, kA + (uint32_t)((jp * 16 * PITCH) << 1) + kk * 32);
                mma16816(sc0[2*jp][0], sc0[2*jp][1], sc0[2*jp][2], sc0[2*jp][3],
                         qa[kk][0], qa[kk][1], qa[kk][2], qa[kk][3], b0, b1);
                mma16816(sc0[2*jp+1][0], sc0[2*jp+1][1], sc0[2*jp+1][2], sc0[2*jp+1][3],
                         qa[kk][0], qa[kk][1], qa[kk][2], qa[kk][3], b2, b3);
            }
        }
        if (diag) {
            #pragma unroll
            for (int j = 0; j < 8; j++) {
                int c = mcol0 + j * 8;
                if (c     > mrow0)     sc0[j][0] = -1e30f;
                if (c + 1 > mrow0)     sc0[j][1] = -1e30f;
                if (c     > mrow0 + 8) sc0[j][2] = -1e30f;
                if (c + 1 > mrow0 + 8) sc0[j][3] = -1e30f;
            }
        }
        // max of half 0
        float mt0 = m0, mt1 = m1;
        #pragma unroll
        for (int j = 0; j < 8; j++) {
            mt0 = fmaxf(mt0, fmaxf(sc0[j][0], sc0[j][1]));
            mt1 = fmaxf(mt1, fmaxf(sc0[j][2], sc0[j][3]));
        }
        mt0 = fmaxf(mt0, __shfl_xor_sync(0xffffffffu, mt0, 1));
        mt0 = fmaxf(mt0, __shfl_xor_sync(0xffffffffu, mt0, 2));
        mt1 = fmaxf(mt1, __shfl_xor_sync(0xffffffffu, mt1, 1));
        mt1 = fmaxf(mt1, __shfl_xor_sync(0xffffffffu, mt1, 2));
        const float fh0_0 = exp2f(m0 - mt0);
        const float fh0_1 = exp2f(m1 - mt1);
        m0 = mt0; m1 = mt1;

        // ====== Phase B: S1 = Q K[cols 64:128]^T  ||  exp of half 0 ======
        float sc1[8][4];
        #pragma unroll
        for (int j = 0; j < 8; j++)
            #pragma unroll
            for (int c = 0; c < 4; c++) sc1[j][c] = 0.0f;
        uint32_t ph0[8][2];
        #pragma unroll
        for (int kk = 0; kk < 8; kk++) {
            #pragma unroll
            for (int jp = 0; jp < 4; jp++) {
                uint32_t b0, b1, b2, b3;
                ldsm_x4(b0, b1, b2, b3,
                        kA + (uint32_t)(((jp * 16 + 64) * PITCH) << 1) + kk * 32);
                mma16816(sc1[2*jp][0], sc1[2*jp][1], sc1[2*jp][2], sc1[2*jp][3],
                         qa[kk][0], qa[kk][1], qa[kk][2], qa[kk][3], b0, b1);
                mma16816(sc1[2*jp+1][0], sc1[2*jp+1][1], sc1[2*jp+1][2], sc1[2*jp+1][3],
                         qa[kk][0], qa[kk][1], qa[kk][2], qa[kk][3], b2, b3);
            }
            // interleaved: exponentials for two j of half 0
            #pragma unroll
            for (int u = 0; u < 2; u++) {
                const int j = 2 * kk + u;
                float d0 = sc0[j][0] - m0, d1 = sc0[j][1] - m0;
                float d2 = sc0[j][2] - m1, d3 = sc0[j][3] - m1;
                ph0[j][0] = ex2h2(h2u(__floats2half2_rn(d0, d1)));
                ph0[j][1] = ex2h2(h2u(__floats2half2_rn(d2, d3)));
            }
        }

        // row sums of half 0 via ones-MMA (reduces across quad too)
        float rsA[4] = {0.0f, 0.0f, 0.0f, 0.0f};
        #pragma unroll
        for (int kp = 0; kp < 4; kp++)
            mma16816(rsA[0], rsA[1], rsA[2], rsA[3],
                     ph0[2*kp][0], ph0[2*kp][1], ph0[2*kp+1][0], ph0[2*kp+1][1],
                     ONES2, ONES2);

        if (diag) {
            #pragma unroll
            for (int j = 0; j < 8; j++) {
                int c = 64 + mcol0 + j * 8;
                if (c     > mrow0)     sc1[j][0] = -1e30f;
                if (c + 1 > mrow0)     sc1[j][1] = -1e30f;
                if (c     > mrow0 + 8) sc1[j][2] = -1e30f;
                if (c + 1 > mrow0 + 8) sc1[j][3] = -1e30f;
            }
        }
        // max of half 1
        mt0 = m0; mt1 = m1;
        #pragma unroll
        for (int j = 0; j < 8; j++) {
            mt0 = fmaxf(mt0, fmaxf(sc1[j][0], sc1[j][1]));
            mt1 = fmaxf(mt1, fmaxf(sc1[j][2], sc1[j][3]));
        }
        mt0 = fmaxf(mt0, __shfl_xor_sync(0xffffffffu, mt0, 1));
        mt0 = fmaxf(mt0, __shfl_xor_sync(0xffffffffu, mt0, 2));
        mt1 = fmaxf(mt1, __shfl_xor_sync(0xffffffffu, mt1, 1));
        mt1 = fmaxf(mt1, __shfl_xor_sync(0xffffffffu, mt1, 2));
        const float fh1_0 = exp2f(m0 - mt0);
        const float fh1_1 = exp2f(m1 - mt1);
        m0 = mt0; m1 = mt1;

        // rescale acc by half-0 factors; update l with half-0 sums
        #pragma unroll
        for (int n = 0; n < 16; n++) {
            acc[n][0] *= fh0_0; acc[n][1] *= fh0_0;
            acc[n][2] *= fh0_1; acc[n][3] *= fh0_1;
        }
        l0 = l0 * fh0_0 + rsA[0];
        l1 = l1 * fh0_1 + rsA[2];

        // ====== Phase C: acc += P0 V[rows 0:64]  ||  exp of half 1 ======
        uint32_t ph1[8][2];
        #pragma unroll
        for (int kk = 0; kk < 4; kk++) {
            const uint32_t a0 = ph0[2*kk][0], a1 = ph0[2*kk][1];
            const uint32_t a2 = ph0[2*kk+1][0], a3 = ph0[2*kk+1][1];
            #pragma unroll
            for (int np = 0; np < 8; np++) {
                uint32_t b0, b1, b2, b3;
                ldsm_x4t(b0, b1, b2, b3,
                         vA + (uint32_t)(((kk * 16 * PITCH) + np * 16) << 1));
                mma16816(acc[2*np][0], acc[2*np][1], acc[2*np][2], acc[2*np][3],
                         a0, a1, a2, a3, b0, b1);
                mma16816(acc[2*np+1][0], acc[2*np+1][1], acc[2*np+1][2], acc[2*np+1][3],
                         a0, a1, a2, a3, b2, b3);
            }
            // interleaved: exponentials for four j of half 1
            #pragma unroll
            for (int u = 0; u < 4; u++) {
                const int j = 4 * kk + u;
                float d0 = sc1[j][0] - m0, d1 = sc1[j][1] - m0;
                float d2 = sc1[j][2] - m1, d3 = sc1[j][3] - m1;
                ph1[j][0] = ex2h2(h2u(__floats2half2_rn(d0, d1)));
                ph1[j][1] = ex2h2(h2u(__floats2half2_rn(d2, d3)));
            }
        }

        // row sums of half 1 via ones-MMA
        float rsB[4] = {0.0f, 0.0f, 0.0f, 0.0f};
        #pragma unroll
        for (int kp = 0; kp < 4; kp++)
            mma16816(rsB[0], rsB[1], rsB[2], rsB[3],
                     ph1[2*kp][0], ph1[2*kp][1], ph1[2*kp+1][0], ph1[2*kp+1][1],
                     ONES2, ONES2);

        // rescale acc by half-1 factors; update l
        #pragma unroll
        for (int n = 0; n < 16; n++) {
            acc[n][0] *= fh1_0; acc[n][1] *= fh1_0;
            acc[n][2] *= fh1_1; acc[n][3] *= fh1_1;
        }
        l0 = l0 * fh1_0 + rsB[0];
        l1 = l1 * fh1_1 + rsB[2];

        // ================= Phase D: acc += P1 V[rows 64:128] =================
        #pragma unroll
        for (int kk = 0; kk < 4; kk++) {
            const uint32_t a0 = ph1[2*kk][0], a1 = ph1[2*kk][1];
            const uint32_t a2 = ph1[2*kk+1][0], a3 = ph1[2*kk+1][1];
            #pragma unroll
            for (int np = 0; np < 8; np++) {
                uint32_t b0, b1, b2, b3;
                ldsm_x4t(b0, b1, b2, b3,
                         vA + (uint32_t)((((kk + 4) * 16 * PITCH) + np * 16) << 1));
                mma16816(acc[2*np][0], acc[2*np][1], acc[2*np][2], acc[2*np][3],
                         a0, a1, a2, a3, b0, b1);
                mma16816(acc[2*np+1][0], acc[2*np+1][1], acc[2*np+1][2], acc[2*np+1][3],
                         a0, a1, a2, a3, b2, b3);
            }
        }

        __syncthreads();
        if (kt + 2 < NT) {
            const int nb = (kt + 2) * BN;
            #pragma unroll
            for (int i = 0; i < 8; i++) {
                int r = lr + i * 16;
                uint32_t off = (uint32_t)((r * PITCH + lc * 8) << 1);
                cp16(kStage[stage] + off, kg + (size_t)(nb + r) * KS + lc * 8);
                cp16(vStage[stage] + off, vg + (size_t)(nb + r) * KS + lc * 8);
            }
        }
        cp_commit();
    }

    // ---- Epilogue (l already quad-reduced by the ones-MMA) ----
    const float inv0 = 1.0f / l0;
    const float inv1 = 1.0f / l1;

    const size_t r0 = (size_t)qbase + warp * 16 + (lane >> 2);
    float* og0 = O + r0 * QS + (size_t)b * HQ * DH + (size_t)h * DH + (lane & 3) * 2;
    float* og1 = og0 + (size_t)8 * QS;
    #pragma unroll
    for (int n = 0; n < 16; n++) {
        *(float2*)(og0 + n * 8) = make_float2(acc[n][0] * inv0, acc[n][1] * inv0);
        *(float2*)(og1 + n * 8) = make_float2(acc[n][2] * inv1, acc[n][3] * inv1);
    }
}

extern "C" void kernel_launch(void* const* d_in, const int* in_sizes, int n_in,
                              void* d_out, int out_size)
{
    const float* Q = (const float*)d_in[0];
    const float* K = (const float*)d_in[1];
    const float* V = (const float*)d_in[2];
    float* O = (float*)d_out;

    convert_kv_kernel<<<KV_ELEMS / 4 / 256, 256>>>(K, V);

    cudaFuncSetAttribute(fa_hmma4_kernel,
                         cudaFuncAttributeMaxDynamicSharedMemorySize,
                         (int)SMEM_BYTES);
    dim3 grid(S_LEN / BM, HQ, BATCH);  // (16, 32, 2) = 1024 CTAs
    fa_hmma4_kernel<<<grid, NTHREADS, SMEM_BYTES>>>(Q, O);
}

// round 7
// speedup vs baseline: 14.4795x; 1.1064x over previous
#include <cuda_runtime.h>
#include <cuda_fp16.h>
#include <cstdint>

// Problem constants: S=2048, B=2, HQ=32, HKV=8, D=128
#define S_LEN 2048
#define BATCH 2
#define HQ 32
#define HKV 8
#define DH 128
#define GROUP 4
// 1/sqrt(128) * log2(e)  — logits land in exp2 domain
#define QSCALE 0.1275325340386934f

#define BM 128               // query tile (8 warps x 16 rows)
#define BN 128               // key tile (two 64-col halves, software pipelined)
#define NTHREADS 256
#define QPITCH 136           // Q staging pitch (halves)

#define QS (BATCH * HQ * DH)   // 8192 floats per seq step (Q/O)

#define TILE_HALVES 16384      // 128 rows x 128 halves (one 32KB tile)
#define TILE_BYTES  32768
#define HEAD_TILES  (S_LEN / BN)   // 16
#define KV_HALVES (S_LEN * BATCH * HKV * DH)

// fp16 K/V, per-head contiguous, blocked-atom SW128 pre-swizzled tiles
__device__ __align__(1024) __half g_Kh[KV_HALVES];
__device__ __align__(1024) __half g_Vh[KV_HALVES];

// smem: [K0 | V0 | K1 | V1] 32KB each, mbarriers at +131072
#define SMEM_BYTES (4 * TILE_BYTES + 16)

#define ONES2 0x3C003C00u    // half2(1.0, 1.0)

// Blocked-atom SW128 byte offset inside a 128x128-half tile.
// atom = 8 rows x 64 halves (1KB); atoms: 16 row-atoms, 2 col-atoms (col-atom stride 16KB)
__host__ __device__ __forceinline__ uint32_t swa(int row, int colH) {
    return (uint32_t)(((((row >> 3) + ((colH >> 6) << 4)) << 10))
                      + ((row & 7) << 7)
                      + (((colH & 63) << 1) ^ ((row & 7) << 4)));
}

__device__ __forceinline__ uint32_t smem_u32(const void* p) {
    uint32_t a;
    asm("{ .reg .u64 t; cvta.to.shared.u64 t, %1; cvt.u32.u64 %0, t; }"
        : "=r"(a) : "l"(p));
    return a;
}
__device__ __forceinline__ void bulk_g2s(uint32_t dst, const void* src,
                                         uint32_t bytes, uint32_t mbar) {
    asm volatile(
        "cp.async.bulk.shared::cta.global.mbarrier::complete_tx::bytes [%0], [%1], %2, [%3];"
        :: "r"(dst), "l"(src), "r"(bytes), "r"(mbar) : "memory");
}
__device__ __forceinline__ void mbar_init(uint32_t a, uint32_t cnt) {
    asm volatile("mbarrier.init.shared.b64 [%0], %1;" :: "r"(a), "r"(cnt) : "memory");
}
__device__ __forceinline__ void mbar_expect(uint32_t a, uint32_t tx) {
    asm volatile("mbarrier.arrive.expect_tx.shared.b64 _, [%0], %1;"
                 :: "r"(a), "r"(tx) : "memory");
}
__device__ __forceinline__ void mbar_wait(uint32_t a, uint32_t phase) {
    asm volatile(
        "{\n\t"
        ".reg .pred P;\n\t"
        "WL_%=:\n\t"
        "mbarrier.try_wait.parity.acquire.cta.shared::cta.b64 P, [%0], %1, 0x989680;\n\t"
        "@P bra.uni WD_%=;\n\t"
        "bra.uni WL_%=;\n\t"
        "WD_%=:\n\t"
        "}"
        :: "r"(a), "r"(phase) : "memory");
}
__device__ __forceinline__ void ldsm_x4(uint32_t& r0, uint32_t& r1, uint32_t& r2,
                                        uint32_t& r3, uint32_t a) {
    asm volatile("ldmatrix.sync.aligned.m8n8.x4.shared.b16 {%0,%1,%2,%3}, [%4];"
                 : "=r"(r0), "=r"(r1), "=r"(r2), "=r"(r3) : "r"(a));
}
__device__ __forceinline__ void ldsm_x4t(uint32_t& r0, uint32_t& r1, uint32_t& r2,
                                         uint32_t& r3, uint32_t a) {
    asm volatile("ldmatrix.sync.aligned.m8n8.x4.trans.shared.b16 {%0,%1,%2,%3}, [%4];"
                 : "=r"(r0), "=r"(r1), "=r"(r2), "=r"(r3) : "r"(a));
}
__device__ __forceinline__ void mma16816(float& c0, float& c1, float& c2, float& c3,
                                         uint32_t a0, uint32_t a1, uint32_t a2,
                                         uint32_t a3, uint32_t b0, uint32_t b1) {
    asm volatile(
        "mma.sync.aligned.m16n8k16.row.col.f32.f16.f16.f32 "
        "{%0,%1,%2,%3}, {%4,%5,%6,%7}, {%8,%9}, {%0,%1,%2,%3};"
        : "+f"(c0), "+f"(c1), "+f"(c2), "+f"(c3)
        : "r"(a0), "r"(a1), "r"(a2), "r"(a3), "r"(b0), "r"(b1));
}
__device__ __forceinline__ uint32_t h2u(__half2 h) {
    return *reinterpret_cast<uint32_t*>(&h);
}
__device__ __forceinline__ uint32_t ex2h2(uint32_t x) {
    uint32_t r;
    asm("ex2.approx.f16x2 %0, %1;" : "=r"(r) : "r"(x));
    return r;
}

// ---- Pre-pass: fp32 K,V -> fp16, per-head contiguous, pre-swizzled tiles ----
// g_Kh layout: [b][hkv][tile s/128][blocked-atom SW128 within 32KB tile]
__global__ void __launch_bounds__(256)
convert_kv_kernel(const float* __restrict__ K, const float* __restrict__ V)
{
    const int cid = blockIdx.x * 256 + threadIdx.x;  // one 16B chunk each
    const int c8 = cid & 15;          // d-chunk (8 halves)
    const int h  = (cid >> 4) & 7;
    const int b  = (cid >> 7) & 1;
    const int s  = cid >> 8;

    const size_t src = (((size_t)s * BATCH + b) * HKV + h) * DH + c8 * 8;
    float4 k0 = *(const float4*)(K + src);
    float4 k1 = *(const float4*)(K + src + 4);
    float4 v0 = *(const float4*)(V + src);
    float4 v1 = *(const float4*)(V + src + 4);

    uint4 kp, vp;
    kp.x = h2u(__floats2half2_rn(k0.x, k0.y));
    kp.y = h2u(__floats2half2_rn(k0.z, k0.w));
    kp.z = h2u(__floats2half2_rn(k1.x, k1.y));
    kp.w = h2u(__floats2half2_rn(k1.z, k1.w));
    vp.x = h2u(__floats2half2_rn(v0.x, v0.y));
    vp.y = h2u(__floats2half2_rn(v0.z, v0.w));
    vp.z = h2u(__floats2half2_rn(v1.x, v1.y));
    vp.w = h2u(__floats2half2_rn(v1.z, v1.w));

    const size_t headB = ((size_t)b * HKV + h) * (HEAD_TILES * TILE_BYTES);
    const size_t off = headB + (size_t)(s >> 7) * TILE_BYTES + swa(s & 127, c8 * 8);
    *(uint4*)((char*)g_Kh + off) = kp;
    *(uint4*)((char*)g_Vh + off) = vp;
}

__global__ void __launch_bounds__(NTHREADS, 1)
fa_hmma5_kernel(const float* __restrict__ Q, float* __restrict__ O)
{
    extern __shared__ __half sm[];
    const uint32_t smBase = smem_u32(sm);

    const int tid = threadIdx.x;
    const int warp = tid >> 5;
    const int lane = tid & 31;

    const int qblock = (S_LEN / BM - 1) - blockIdx.x;  // heavy blocks first
    const int h = blockIdx.y, b = blockIdx.z;
    const int hk = h / GROUP;
    const int qbase = qblock * BM;
    const int NT = qblock + 1;

    const __half* kg = g_Kh + ((size_t)b * HKV + hk) * (HEAD_TILES * TILE_HALVES);
    const __half* vg = g_Vh + ((size_t)b * HKV + hk) * (HEAD_TILES * TILE_HALVES);

    const uint32_t kStage[2] = { smBase,                 smBase + 2u * TILE_BYTES };
    const uint32_t vStage[2] = { smBase + 1u * TILE_BYTES, smBase + 3u * TILE_BYTES };
    const uint32_t mbarBase = smBase + 4u * TILE_BYTES;

    if (tid == 0) {
        mbar_init(mbarBase, 1);
        mbar_init(mbarBase + 8, 1);
    }

    // ---- Stage Q (fp32 -> scaled fp16, pitch QPITCH) in stage area; ldsm to regs ----
    uint32_t qa[8][4];
    {
        const float* qg = Q + (size_t)qbase * QS + (size_t)b * HQ * DH + (size_t)h * DH;
        #pragma unroll
        for (int i = 0; i < 16; i++) {
            int e = tid + i * NTHREADS;
            int r = e >> 5, c4 = e & 31;
            float4 v = *(const float4*)(qg + (size_t)r * QS + c4 * 4);
            *(__half2*)(sm + r * QPITCH + c4 * 4)     = __floats2half2_rn(v.x * QSCALE, v.y * QSCALE);
            *(__half2*)(sm + r * QPITCH + c4 * 4 + 2) = __floats2half2_rn(v.z * QSCALE, v.w * QSCALE);
        }
        __syncthreads();   // Q staged + mbar init visible
        const uint32_t qAddr = smBase +
            (((warp * 16 + (lane & 15)) * QPITCH + (lane >> 4) * 8) << 1);
        #pragma unroll
        for (int kk = 0; kk < 8; kk++)
            ldsm_x4(qa[kk][0], qa[kk][1], qa[kk][2], qa[kk][3], qAddr + kk * 32);
        __syncthreads();   // Q reads done before bulk copies overwrite stages
    }

    // ---- Prologue: bulk-prefetch tiles 0 and 1 ----
    if (tid == 0) {
        #pragma unroll
        for (int t = 0; t < 2; t++) {
            if (t < NT) {
                const uint32_t mb = mbarBase + t * 8;
                mbar_expect(mb, 2 * TILE_BYTES);
                bulk_g2s(kStage[t], kg + (size_t)t * TILE_HALVES, TILE_BYTES, mb);
                bulk_g2s(vStage[t], vg + (size_t)t * TILE_HALVES, TILE_BYTES, mb);
            }
        }
    }

    float acc[16][4];
    #pragma unroll
    for (int n = 0; n < 16; n++)
        #pragma unroll
        for (int c = 0; c < 4; c++) acc[n][c] = 0.0f;
    float m0 = -1e30f, m1 = -1e30f, l0 = 0.0f, l1 = 0.0f;

    const int mrow0 = warp * 16 + (lane >> 2);
    const int mcol0 = (lane & 3) * 2;
    // per-lane ldmatrix row/col components
    const int kRowL = (lane & 7) + ((lane >> 4) << 3);      // K frag row within 16
    const int kColL = (((lane & 15) >> 3) << 3);            // K frag col within 16
    const int vRowL = (lane & 15);                          // V frag row within 16
    const int vColL = ((lane >> 4) << 3);                   // V frag col within 16

    for (int kt = 0; kt < NT; kt++) {
        const int stage = kt & 1;
        mbar_wait(mbarBase + stage * 8, (kt >> 1) & 1);

        const uint32_t kB = kStage[stage];
        const uint32_t vB = vStage[stage];
        const bool diag = (kt == qblock);

        // ================= Phase A: S0 = Q K[rows 0:64]^T =================
        float sc0[8][4];
        #pragma unroll
        for (int j = 0; j < 8; j++)
            #pragma unroll
            for (int c = 0; c < 4; c++) sc0[j][c] = 0.0f;
        #pragma unroll
        for (int kk = 0; kk < 8; kk++) {
            #pragma unroll
            for (int jp = 0; jp < 4; jp++) {
                uint32_t b0, b1, b2, b3;
                ldsm_x4(b0, b1, b2, b3, kB + swa(jp * 16 + kRowL, kk * 16 + kColL));
                mma16816(sc0[2*jp][0], sc0[2*jp][1], sc0[2*jp][2], sc0[2*jp][3],
                         qa[kk][0], qa[kk][1], qa[kk][2], qa[kk][3], b0, b1);
                mma16816(sc0[2*jp+1][0], sc0[2*jp+1][1], sc0[2*jp+1][2], sc0[2*jp+1][3],
                         qa[kk][0], qa[kk][1], qa[kk][2], qa[kk][3], b2, b3);
            }
        }
        if (diag) {
            #pragma unroll
            for (int j = 0; j < 8; j++) {
                int c = mcol0 + j * 8;
                if (c     > mrow0)     sc0[j][0] = -1e30f;
                if (c + 1 > mrow0)     sc0[j][1] = -1e30f;
                if (c     > mrow0 + 8) sc0[j][2] = -1e30f;
                if (c + 1 > mrow0 + 8) sc0[j][3] = -1e30f;
            }
        }
        float mt0 = m0, mt1 = m1;
        #pragma unroll
        for (int j = 0; j < 8; j++) {
            mt0 = fmaxf(mt0, fmaxf(sc0[j][0], sc0[j][1]));
            mt1 = fmaxf(mt1, fmaxf(sc0[j][2], sc0[j][3]));
        }
        mt0 = fmaxf(mt0, __shfl_xor_sync(0xffffffffu, mt0, 1));
        mt0 = fmaxf(mt0, __shfl_xor_sync(0xffffffffu, mt0, 2));
        mt1 = fmaxf(mt1, __shfl_xor_sync(0xffffffffu, mt1, 1));
        mt1 = fmaxf(mt1, __shfl_xor_sync(0xffffffffu, mt1, 2));
        const float fh0_0 = exp2f(m0 - mt0);
        const float fh0_1 = exp2f(m1 - mt1);
        m0 = mt0; m1 = mt1;

        // ====== Phase B: S1 = Q K[rows 64:128]^T  ||  exp of half 0 ======
        float sc1[8][4];
        #pragma unroll
        for (int j = 0; j < 8; j++)
            #pragma unroll
            for (int c = 0; c < 4; c++) sc1[j][c] = 0.0f;
        uint32_t ph0[8][2];
        #pragma unroll
        for (int kk = 0; kk < 8; kk++) {
            #pragma unroll
            for (int jp = 0; jp < 4; jp++) {
                uint32_t b0, b1, b2, b3;
                ldsm_x4(b0, b1, b2, b3,
                        kB + swa(64 + jp * 16 + kRowL, kk * 16 + kColL));
                mma16816(sc1[2*jp][0], sc1[2*jp][1], sc1[2*jp][2], sc1[2*jp][3],
                         qa[kk][0], qa[kk][1], qa[kk][2], qa[kk][3], b0, b1);
                mma16816(sc1[2*jp+1][0], sc1[2*jp+1][1], sc1[2*jp+1][2], sc1[2*jp+1][3],
                         qa[kk][0], qa[kk][1], qa[kk][2], qa[kk][3], b2, b3);
            }
            #pragma unroll
            for (int u = 0; u < 2; u++) {
                const int j = 2 * kk + u;
                float d0 = sc0[j][0] - m0, d1 = sc0[j][1] - m0;
                float d2 = sc0[j][2] - m1, d3 = sc0[j][3] - m1;
                ph0[j][0] = ex2h2(h2u(__floats2half2_rn(d0, d1)));
                ph0[j][1] = ex2h2(h2u(__floats2half2_rn(d2, d3)));
            }
        }

        float rsA[4] = {0.0f, 0.0f, 0.0f, 0.0f};
        #pragma unroll
        for (int kp = 0; kp < 4; kp++)
            mma16816(rsA[0], rsA[1], rsA[2], rsA[3],
                     ph0[2*kp][0], ph0[2*kp][1], ph0[2*kp+1][0], ph0[2*kp+1][1],
                     ONES2, ONES2);

        if (diag) {
            #pragma unroll
            for (int j = 0; j < 8; j++) {
                int c = 64 + mcol0 + j * 8;
                if (c     > mrow0)     sc1[j][0] = -1e30f;
                if (c + 1 > mrow0)     sc1[j][1] = -1e30f;
                if (c     > mrow0 + 8) sc1[j][2] = -1e30f;
                if (c + 1 > mrow0 + 8) sc1[j][3] = -1e30f;
            }
        }
        mt0 = m0; mt1 = m1;
        #pragma unroll
        for (int j = 0; j < 8; j++) {
            mt0 = fmaxf(mt0, fmaxf(sc1[j][0], sc1[j][1]));
            mt1 = fmaxf(mt1, fmaxf(sc1[j][2], sc1[j][3]));
        }
        mt0 = fmaxf(mt0, __shfl_xor_sync(0xffffffffu, mt0, 1));
        mt0 = fmaxf(mt0, __shfl_xor_sync(0xffffffffu, mt0, 2));
        mt1 = fmaxf(mt1, __shfl_xor_sync(0xffffffffu, mt1, 1));
        mt1 = fmaxf(mt1, __shfl_xor_sync(0xffffffffu, mt1, 2));
        const float fh1_0 = exp2f(m0 - mt0);
        const float fh1_1 = exp2f(m1 - mt1);
        m0 = mt0; m1 = mt1;

        #pragma unroll
        for (int n = 0; n < 16; n++) {
            acc[n][0] *= fh0_0; acc[n][1] *= fh0_0;
            acc[n][2] *= fh0_1; acc[n][3] *= fh0_1;
        }
        l0 = l0 * fh0_0 + rsA[0];
        l1 = l1 * fh0_1 + rsA[2];

        // ====== Phase C: acc += P0 V[rows 0:64]  ||  exp of half 1 ======
        uint32_t ph1[8][2];
        #pragma unroll
        for (int kk = 0; kk < 4; kk++) {
            const uint32_t a0 = ph0[2*kk][0], a1 = ph0[2*kk][1];
            const uint32_t a2 = ph0[2*kk+1][0], a3 = ph0[2*kk+1][1];
            #pragma unroll
            for (int np = 0; np < 8; np++) {
                uint32_t b0, b1, b2, b3;
                ldsm_x4t(b0, b1, b2, b3,
                         vB + swa(kk * 16 + vRowL, np * 16 + vColL));
                mma16816(acc[2*np][0], acc[2*np][1], acc[2*np][2], acc[2*np][3],
                         a0, a1, a2, a3, b0, b1);
                mma16816(acc[2*np+1][0], acc[2*np+1][1], acc[2*np+1][2], acc[2*np+1][3],
                         a0, a1, a2, a3, b2, b3);
            }
            #pragma unroll
            for (int u = 0; u < 4; u++) {
                const int j = 4 * kk + u;
                float d0 = sc1[j][0] - m0, d1 = sc1[j][1] - m0;
                float d2 = sc1[j][2] - m1, d3 = sc1[j][3] - m1;
                ph1[j][0] = ex2h2(h2u(__floats2half2_rn(d0, d1)));
                ph1[j][1] = ex2h2(h2u(__floats2half2_rn(d2, d3)));
            }
        }

        float rsB[4] = {0.0f, 0.0f, 0.0f, 0.0f};
        #pragma unroll
        for (int kp = 0; kp < 4; kp++)
            mma16816(rsB[0], rsB[1], rsB[2], rsB[3],
                     ph1[2*kp][0], ph1[2*kp][1], ph1[2*kp+1][0], ph1[2*kp+1][1],
                     ONES2, ONES2);

        #pragma unroll
        for (int n = 0; n < 16; n++) {
            acc[n][0] *= fh1_0; acc[n][1] *= fh1_0;
            acc[n][2] *= fh1_1; acc[n][3] *= fh1_1;
        }
        l0 = l0 * fh1_0 + rsB[0];
        l1 = l1 * fh1_1 + rsB[2];

        // ================= Phase D: acc += P1 V[rows 64:128] =================
        #pragma unroll
        for (int kk = 0; kk < 4; kk++) {
            const uint32_t a0 = ph1[2*kk][0], a1 = ph1[2*kk][1];
            const uint32_t a2 = ph1[2*kk+1][0], a3 = ph1[2*kk+1][1];
            #pragma unroll
            for (int np = 0; np < 8; np++) {
                uint32_t b0, b1, b2, b3;
                ldsm_x4t(b0, b1, b2, b3,
                         vB + swa((kk + 4) * 16 + vRowL, np * 16 + vColL));
                mma16816(acc[2*np][0], acc[2*np][1], acc[2*np][2], acc[2*np][3],
                         a0, a1, a2, a3, b0, b1);
                mma16816(acc[2*np+1][0], acc[2*np+1][1], acc[2*np+1][2], acc[2*np+1][3],
                         a0, a1, a2, a3, b2, b3);
            }
        }

        __syncthreads();   // all warps done reading this stage
        if (tid == 0 && kt + 2 < NT) {
            const uint32_t mb = mbarBase + stage * 8;
            mbar_expect(mb, 2 * TILE_BYTES);
            bulk_g2s(kB, kg + (size_t)(kt + 2) * TILE_HALVES, TILE_BYTES, mb);
            bulk_g2s(vB, vg + (size_t)(kt + 2) * TILE_HALVES, TILE_BYTES, mb);
        }
    }

    // ---- Epilogue (l already quad-reduced by the ones-MMA) ----
    const float inv0 = 1.0f / l0;
    const float inv1 = 1.0f / l1;

    const size_t r0 = (size_t)qbase + warp * 16 + (lane >> 2);
    float* og0 = O + r0 * QS + (size_t)b * HQ * DH + (size_t)h * DH + (lane & 3) * 2;
    float* og1 = og0 + (size_t)8 * QS;
    #pragma unroll
    for (int n = 0; n < 16; n++) {
        *(float2*)(og0 + n * 8) = make_float2(acc[n][0] * inv0, acc[n][1] * inv0);
        *(float2*)(og1 + n * 8) = make_float2(acc[n][2] * inv1, acc[n][3] * inv1);
    }
}

extern "C" void kernel_launch(void* const* d_in, const int* in_sizes, int n_in,
                              void* d_out, int out_size)
{
    const float* Q = (const float*)d_in[0];
    const float* K = (const float*)d_in[1];
    const float* V = (const float*)d_in[2];
    float* O = (float*)d_out;

    convert_kv_kernel<<<KV_HALVES / 8 / 256, 256>>>(K, V);

    cudaFuncSetAttribute(fa_hmma5_kernel,
                         cudaFuncAttributeMaxDynamicSharedMemorySize,
                         (int)SMEM_BYTES);
    dim3 grid(S_LEN / BM, HQ, BATCH);  // (16, 32, 2) = 1024 CTAs
    fa_hmma5_kernel<<<grid, NTHREADS, SMEM_BYTES>>>(Q, O);
}

// round 9
// speedup vs baseline: 14.7073x; 1.0157x over previous
#include <cuda_runtime.h>
#include <cuda_fp16.h>
#include <cstdint>

// Problem constants: S=2048, B=2, HQ=32, HKV=8, D=128
#define S_LEN 2048
#define BATCH 2
#define HQ 32
#define HKV 8
#define DH 128
#define GROUP 4
// 1/sqrt(128) * log2(e)  — logits land in exp2 domain
#define QSCALE 0.1275325340386934f

#define BM 128               // query tile (8 warps x 16 rows)
#define BN 128               // key tile (two 64-col halves, software pipelined)
#define NTHREADS 256
#define QPITCH 136           // Q staging pitch (halves)

#define QS (BATCH * HQ * DH)   // 8192 floats per seq step (Q/O)

#define TILE_HALVES 16384      // 128 rows x 128 halves (one 32KB tile)
#define TILE_BYTES  32768
#define HEAD_TILES  (S_LEN / BN)   // 16
#define KV_HALVES (S_LEN * BATCH * HKV * DH)

// fp16 K/V, per-head contiguous, blocked-atom SW128 pre-swizzled tiles
__device__ __align__(1024) __half g_Kh[KV_HALVES];
__device__ __align__(1024) __half g_Vh[KV_HALVES];

// smem: [K0 | V0 | K1 | V1] 32KB each, mbarriers at +131072
#define SMEM_BYTES (4 * TILE_BYTES + 16)

#define ONES2 0x3C003C00u    // half2(1.0, 1.0)

// Blocked-atom SW128 byte offset inside a 128x128-half tile.
// atom = 8 rows x 64 halves (1KB); atoms: 16 row-atoms, 2 col-atoms (+16KB)
__host__ __device__ __forceinline__ uint32_t swa(int row, int colH) {
    return (uint32_t)(((((row >> 3) + ((colH >> 6) << 4)) << 10))
                      + ((row & 7) << 7)
                      + (((colH & 63) << 1) ^ ((row & 7) << 4)));
}

__device__ __forceinline__ uint32_t smem_u32(const void* p) {
    uint32_t a;
    asm("{ .reg .u64 t; cvta.to.shared.u64 t, %1; cvt.u32.u64 %0, t; }"
        : "=r"(a) : "l"(p));
    return a;
}
__device__ __forceinline__ void bulk_g2s(uint32_t dst, const void* src,
                                         uint32_t bytes, uint32_t mbar) {
    asm volatile(
        "cp.async.bulk.shared::cta.global.mbarrier::complete_tx::bytes [%0], [%1], %2, [%3];"
        :: "r"(dst), "l"(src), "r"(bytes), "r"(mbar) : "memory");
}
__device__ __forceinline__ void mbar_init(uint32_t a, uint32_t cnt) {
    asm volatile("mbarrier.init.shared.b64 [%0], %1;" :: "r"(a), "r"(cnt) : "memory");
}
__device__ __forceinline__ void mbar_expect(uint32_t a, uint32_t tx) {
    asm volatile("mbarrier.arrive.expect_tx.shared.b64 _, [%0], %1;"
                 :: "r"(a), "r"(tx) : "memory");
}
__device__ __forceinline__ void mbar_wait(uint32_t a, uint32_t phase) {
    asm volatile(
        "{\n\t"
        ".reg .pred P;\n\t"
        "WL_%=:\n\t"
        "mbarrier.try_wait.parity.acquire.cta.shared::cta.b64 P, [%0], %1, 0x989680;\n\t"
        "@P bra.uni WD_%=;\n\t"
        "bra.uni WL_%=;\n\t"
        "WD_%=:\n\t"
        "}"
        :: "r"(a), "r"(phase) : "memory");
}
// NON-volatile ldmatrix: "memory" clobber keeps it ordered against barriers,
// but ptxas may schedule dependent MMAs freely (software pipelining).
__device__ __forceinline__ void ldsm_x4(uint32_t& r0, uint32_t& r1, uint32_t& r2,
                                        uint32_t& r3, uint32_t a) {
    asm("ldmatrix.sync.aligned.m8n8.x4.shared.b16 {%0,%1,%2,%3}, [%4];"
        : "=r"(r0), "=r"(r1), "=r"(r2), "=r"(r3) : "r"(a) : "memory");
}
__device__ __forceinline__ void ldsm_x4t(uint32_t& r0, uint32_t& r1, uint32_t& r2,
                                         uint32_t& r3, uint32_t a) {
    asm("ldmatrix.sync.aligned.m8n8.x4.trans.shared.b16 {%0,%1,%2,%3}, [%4];"
        : "=r"(r0), "=r"(r1), "=r"(r2), "=r"(r3) : "r"(a) : "memory");
}
// NON-volatile mma: register-only dataflow, fully reschedulable.
__device__ __forceinline__ void mma16816(float& c0, float& c1, float& c2, float& c3,
                                         uint32_t a0, uint32_t a1, uint32_t a2,
                                         uint32_t a3, uint32_t b0, uint32_t b1) {
    asm("mma.sync.aligned.m16n8k16.row.col.f32.f16.f16.f32 "
        "{%0,%1,%2,%3}, {%4,%5,%6,%7}, {%8,%9}, {%0,%1,%2,%3};"
        : "+f"(c0), "+f"(c1), "+f"(c2), "+f"(c3)
        : "r"(a0), "r"(a1), "r"(a2), "r"(a3), "r"(b0), "r"(b1));
}
__device__ __forceinline__ uint32_t h2u(__half2 h) {
    return *reinterpret_cast<uint32_t*>(&h);
}
__device__ __forceinline__ uint32_t ex2h2(uint32_t x) {
    uint32_t r;
    asm("ex2.approx.f16x2 %0, %1;" : "=r"(r) : "r"(x));
    return r;
}

// ---- Pre-pass: fp32 K,V -> fp16, per-head contiguous, pre-swizzled tiles ----
__global__ void __launch_bounds__(256)
convert_kv_kernel(const float* __restrict__ K, const float* __restrict__ V)
{
    const int cid = blockIdx.x * 256 + threadIdx.x;  // one 16B chunk each
    const int c8 = cid & 15;
    const int h  = (cid >> 4) & 7;
    const int b  = (cid >> 7) & 1;
    const int s  = cid >> 8;

    const size_t src = (((size_t)s * BATCH + b) * HKV + h) * DH + c8 * 8;
    float4 k0 = *(const float4*)(K + src);
    float4 k1 = *(const float4*)(K + src + 4);
    float4 v0 = *(const float4*)(V + src);
    float4 v1 = *(const float4*)(V + src + 4);

    uint4 kp, vp;
    kp.x = h2u(__floats2half2_rn(k0.x, k0.y));
    kp.y = h2u(__floats2half2_rn(k0.z, k0.w));
    kp.z = h2u(__floats2half2_rn(k1.x, k1.y));
    kp.w = h2u(__floats2half2_rn(k1.z, k1.w));
    vp.x = h2u(__floats2half2_rn(v0.x, v0.y));
    vp.y = h2u(__floats2half2_rn(v0.z, v0.w));
    vp.z = h2u(__floats2half2_rn(v1.x, v1.y));
    vp.w = h2u(__floats2half2_rn(v1.z, v1.w));

    const size_t headB = ((size_t)b * HKV + h) * (HEAD_TILES * TILE_BYTES);
    const size_t off = headB + (size_t)(s >> 7) * TILE_BYTES + swa(s & 127, c8 * 8);
    *(uint4*)((char*)g_Kh + off) = kp;
    *(uint4*)((char*)g_Vh + off) = vp;
}

__global__ void __launch_bounds__(NTHREADS, 1)
fa_hmma6_kernel(const float* __restrict__ Q, float* __restrict__ O)
{
    extern __shared__ __half sm[];
    const uint32_t smBase = smem_u32(sm);

    const int tid = threadIdx.x;
    const int warp = tid >> 5;
    const int lane = tid & 31;

    const int qblock = (S_LEN / BM - 1) - blockIdx.x;  // heavy blocks first
    const int h = blockIdx.y, b = blockIdx.z;
    const int hk = h / GROUP;
    const int qbase = qblock * BM;
    const int NT = qblock + 1;

    const __half* kg = g_Kh + ((size_t)b * HKV + hk) * (HEAD_TILES * TILE_HALVES);
    const __half* vg = g_Vh + ((size_t)b * HKV + hk) * (HEAD_TILES * TILE_HALVES);

    const uint32_t kStage[2] = { smBase,                   smBase + 2u * TILE_BYTES };
    const uint32_t vStage[2] = { smBase + 1u * TILE_BYTES, smBase + 3u * TILE_BYTES };
    const uint32_t mbarBase = smBase + 4u * TILE_BYTES;

    if (tid == 0) {
        mbar_init(mbarBase, 1);
        mbar_init(mbarBase + 8, 1);
    }

    // ---- Stage Q (fp32 -> scaled fp16, pitch QPITCH) in stage area; ldsm to regs ----
    uint32_t qa[8][4];
    {
        const float* qg = Q + (size_t)qbase * QS + (size_t)b * HQ * DH + (size_t)h * DH;
        #pragma unroll
        for (int i = 0; i < 16; i++) {
            int e = tid + i * NTHREADS;
            int r = e >> 5, c4 = e & 31;
            float4 v = *(const float4*)(qg + (size_t)r * QS + c4 * 4);
            *(__half2*)(sm + r * QPITCH + c4 * 4)     = __floats2half2_rn(v.x * QSCALE, v.y * QSCALE);
            *(__half2*)(sm + r * QPITCH + c4 * 4 + 2) = __floats2half2_rn(v.z * QSCALE, v.w * QSCALE);
        }
        __syncthreads();   // Q staged + mbar init visible
        const uint32_t qAddr = smBase +
            (((warp * 16 + (lane & 15)) * QPITCH + (lane >> 4) * 8) << 1);
        #pragma unroll
        for (int kk = 0; kk < 8; kk++)
            ldsm_x4(qa[kk][0], qa[kk][1], qa[kk][2], qa[kk][3], qAddr + kk * 32);
        __syncthreads();   // Q reads done before bulk copies overwrite stages
    }

    // ---- Prologue: bulk-prefetch tiles 0 and 1 ----
    if (tid == 0) {
        #pragma unroll
        for (int t = 0; t < 2; t++) {
            if (t < NT) {
                const uint32_t mb = mbarBase + t * 8;
                mbar_expect(mb, 2 * TILE_BYTES);
                bulk_g2s(kStage[t], kg + (size_t)t * TILE_HALVES, TILE_BYTES, mb);
                bulk_g2s(vStage[t], vg + (size_t)t * TILE_HALVES, TILE_BYTES, mb);
            }
        }
    }

    float acc[16][4];
    #pragma unroll
    for (int n = 0; n < 16; n++)
        #pragma unroll
        for (int c = 0; c < 4; c++) acc[n][c] = 0.0f;
    float m0 = -1e30f, m1 = -1e30f, l0 = 0.0f, l1 = 0.0f;

    const int mrow0 = warp * 16 + (lane >> 2);
    const int mcol0 = (lane & 3) * 2;
    const int kRowL = (lane & 7) + ((lane >> 4) << 3);
    const int kColL = (((lane & 15) >> 3) << 3);
    const int vRowL = (lane & 15);
    const int vColL = ((lane >> 4) << 3);

    for (int kt = 0; kt < NT; kt++) {
        const int stage = kt & 1;
        mbar_wait(mbarBase + stage * 8, (kt >> 1) & 1);

        const uint32_t kB = kStage[stage];
        const uint32_t vB = vStage[stage];
        const bool diag = (kt == qblock);

        // ================= Phase A: S0 = Q K[rows 0:64]^T =================
        float sc0[8][4];
        #pragma unroll
        for (int j = 0; j < 8; j++)
            #pragma unroll
            for (int c = 0; c < 4; c++) sc0[j][c] = 0.0f;
        #pragma unroll
        for (int kk = 0; kk < 8; kk++) {
            uint32_t bf[4][4];
            #pragma unroll
            for (int jp = 0; jp < 4; jp++)     // batched loads: MLP=4
                ldsm_x4(bf[jp][0], bf[jp][1], bf[jp][2], bf[jp][3],
                        kB + swa(jp * 16 + kRowL, kk * 16 + kColL));
            #pragma unroll
            for (int jp = 0; jp < 4; jp++) {
                mma16816(sc0[2*jp][0], sc0[2*jp][1], sc0[2*jp][2], sc0[2*jp][3],
                         qa[kk][0], qa[kk][1], qa[kk][2], qa[kk][3],
                         bf[jp][0], bf[jp][1]);
                mma16816(sc0[2*jp+1][0], sc0[2*jp+1][1], sc0[2*jp+1][2], sc0[2*jp+1][3],
                         qa[kk][0], qa[kk][1], qa[kk][2], qa[kk][3],
                         bf[jp][2], bf[jp][3]);
            }
        }
        if (diag) {
            #pragma unroll
            for (int j = 0; j < 8; j++) {
                int c = mcol0 + j * 8;
                if (c     > mrow0)     sc0[j][0] = -1e30f;
                if (c + 1 > mrow0)     sc0[j][1] = -1e30f;
                if (c     > mrow0 + 8) sc0[j][2] = -1e30f;
                if (c + 1 > mrow0 + 8) sc0[j][3] = -1e30f;
            }
        }
        float mt0 = m0, mt1 = m1;
        #pragma unroll
        for (int j = 0; j < 8; j++) {
            mt0 = fmaxf(mt0, fmaxf(sc0[j][0], sc0[j][1]));
            mt1 = fmaxf(mt1, fmaxf(sc0[j][2], sc0[j][3]));
        }
        mt0 = fmaxf(mt0, __shfl_xor_sync(0xffffffffu, mt0, 1));
        mt0 = fmaxf(mt0, __shfl_xor_sync(0xffffffffu, mt0, 2));
        mt1 = fmaxf(mt1, __shfl_xor_sync(0xffffffffu, mt1, 1));
        mt1 = fmaxf(mt1, __shfl_xor_sync(0xffffffffu, mt1, 2));
        const float fh0_0 = exp2f(m0 - mt0);
        const float fh0_1 = exp2f(m1 - mt1);
        m0 = mt0; m1 = mt1;

        // ====== Phase B: S1 = Q K[rows 64:128]^T  ||  exp of half 0 ======
        float sc1[8][4];
        #pragma unroll
        for (int j = 0; j < 8; j++)
            #pragma unroll
            for (int c = 0; c < 4; c++) sc1[j][c] = 0.0f;
        uint32_t ph0[8][2];
        #pragma unroll
        for (int kk = 0; kk < 8; kk++) {
            uint32_t bf[4][4];
            #pragma unroll
            for (int jp = 0; jp < 4; jp++)
                ldsm_x4(bf[jp][0], bf[jp][1], bf[jp][2], bf[jp][3],
                        kB + swa(64 + jp * 16 + kRowL, kk * 16 + kColL));
            #pragma unroll
            for (int jp = 0; jp < 4; jp++) {
                mma16816(sc1[2*jp][0], sc1[2*jp][1], sc1[2*jp][2], sc1[2*jp][3],
                         qa[kk][0], qa[kk][1], qa[kk][2], qa[kk][3],
                         bf[jp][0], bf[jp][1]);
                mma16816(sc1[2*jp+1][0], sc1[2*jp+1][1], sc1[2*jp+1][2], sc1[2*jp+1][3],
                         qa[kk][0], qa[kk][1], qa[kk][2], qa[kk][3],
                         bf[jp][2], bf[jp][3]);
            }
            #pragma unroll
            for (int u = 0; u < 2; u++) {   // interleaved exp of half 0
                const int j = 2 * kk + u;
                float d0 = sc0[j][0] - m0, d1 = sc0[j][1] - m0;
                float d2 = sc0[j][2] - m1, d3 = sc0[j][3] - m1;
                ph0[j][0] = ex2h2(h2u(__floats2half2_rn(d0, d1)));
                ph0[j][1] = ex2h2(h2u(__floats2half2_rn(d2, d3)));
            }
        }

        float rsA[4] = {0.0f, 0.0f, 0.0f, 0.0f};
        #pragma unroll
        for (int kp = 0; kp < 4; kp++)
            mma16816(rsA[0], rsA[1], rsA[2], rsA[3],
                     ph0[2*kp][0], ph0[2*kp][1], ph0[2*kp+1][0], ph0[2*kp+1][1],
                     ONES2, ONES2);

        if (diag) {
            #pragma unroll
            for (int j = 0; j < 8; j++) {
                int c = 64 + mcol0 + j * 8;
                if (c     > mrow0)     sc1[j][0] = -1e30f;
                if (c + 1 > mrow0)     sc1[j][1] = -1e30f;
                if (c     > mrow0 + 8) sc1[j][2] = -1e30f;
                if (c + 1 > mrow0 + 8) sc1[j][3] = -1e30f;
            }
        }
        mt0 = m0; mt1 = m1;
        #pragma unroll
        for (int j = 0; j < 8; j++) {
            mt0 = fmaxf(mt0, fmaxf(sc1[j][0], sc1[j][1]));
            mt1 = fmaxf(mt1, fmaxf(sc1[j][2], sc1[j][3]));
        }
        mt0 = fmaxf(mt0, __shfl_xor_sync(0xffffffffu, mt0, 1));
        mt0 = fmaxf(mt0, __shfl_xor_sync(0xffffffffu, mt0, 2));
        mt1 = fmaxf(mt1, __shfl_xor_sync(0xffffffffu, mt1, 1));
        mt1 = fmaxf(mt1, __shfl_xor_sync(0xffffffffu, mt1, 2));
        const float fh1_0 = exp2f(m0 - mt0);
        const float fh1_1 = exp2f(m1 - mt1);
        m0 = mt0; m1 = mt1;

        #pragma unroll
        for (int n = 0; n < 16; n++) {
            acc[n][0] *= fh0_0; acc[n][1] *= fh0_0;
            acc[n][2] *= fh0_1; acc[n][3] *= fh0_1;
        }
        l0 = l0 * fh0_0 + rsA[0];
        l1 = l1 * fh0_1 + rsA[2];

        // ====== Phase C: acc += P0 V[rows 0:64]  ||  exp of half 1 ======
        uint32_t ph1[8][2];
        #pragma unroll
        for (int kk = 0; kk < 4; kk++) {
            const uint32_t a0 = ph0[2*kk][0], a1 = ph0[2*kk][1];
            const uint32_t a2 = ph0[2*kk+1][0], a3 = ph0[2*kk+1][1];
            #pragma unroll
            for (int ng = 0; ng < 2; ng++) {     // two batches of 4 np
                uint32_t bf[4][4];
                #pragma unroll
                for (int q = 0; q < 4; q++)
                    ldsm_x4t(bf[q][0], bf[q][1], bf[q][2], bf[q][3],
                             vB + swa(kk * 16 + vRowL, (ng * 4 + q) * 16 + vColL));
                #pragma unroll
                for (int q = 0; q < 4; q++) {
                    const int np = ng * 4 + q;
                    mma16816(acc[2*np][0], acc[2*np][1], acc[2*np][2], acc[2*np][3],
                             a0, a1, a2, a3, bf[q][0], bf[q][1]);
                    mma16816(acc[2*np+1][0], acc[2*np+1][1], acc[2*np+1][2], acc[2*np+1][3],
                             a0, a1, a2, a3, bf[q][2], bf[q][3]);
                }
            }
            #pragma unroll
            for (int u = 0; u < 4; u++) {   // interleaved exp of half 1
                const int j = 4 * kk + u;
                float d0 = sc1[j][0] - m0, d1 = sc1[j][1] - m0;
                float d2 = sc1[j][2] - m1, d3 = sc1[j][3] - m1;
                ph1[j][0] = ex2h2(h2u(__floats2half2_rn(d0, d1)));
                ph1[j][1] = ex2h2(h2u(__floats2half2_rn(d2, d3)));
            }
        }

        float rsB[4] = {0.0f, 0.0f, 0.0f, 0.0f};
        #pragma unroll
        for (int kp = 0; kp < 4; kp++)
            mma16816(rsB[0], rsB[1], rsB[2], rsB[3],
                     ph1[2*kp][0], ph1[2*kp][1], ph1[2*kp+1][0], ph1[2*kp+1][1],
                     ONES2, ONES2);

        #pragma unroll
        for (int n = 0; n < 16; n++) {
            acc[n][0] *= fh1_0; acc[n][1] *= fh1_0;
            acc[n][2] *= fh1_1; acc[n][3] *= fh1_1;
        }
        l0 = l0 * fh1_0 + rsB[0];
        l1 = l1 * fh1_1 + rsB[2];

        // ================= Phase D: acc += P1 V[rows 64:128] =================
        #pragma unroll
        for (int kk = 0; kk < 4; kk++) {
            const uint32_t a0 = ph1[2*kk][0], a1 = ph1[2*kk][1];
            const uint32_t a2 = ph1[2*kk+1][0], a3 = ph1[2*kk+1][1];
            #pragma unroll
            for (int ng = 0; ng < 2; ng++) {
                uint32_t bf[4][4];
                #pragma unroll
                for (int q = 0; q < 4; q++)
                    ldsm_x4t(bf[q][0], bf[q][1], bf[q][2], bf[q][3],
                             vB + swa((kk + 4) * 16 + vRowL, (ng * 4 + q) * 16 + vColL));
                #pragma unroll
                for (int q = 0; q < 4; q++) {
                    const int np = ng * 4 + q;
                    mma16816(acc[2*np][0], acc[2*np][1], acc[2*np][2], acc[2*np][3],
                             a0, a1, a2, a3, bf[q][0], bf[q][1]);
                    mma16816(acc[2*np+1][0], acc[2*np+1][1], acc[2*np+1][2], acc[2*np+1][3],
                             a0, a1, a2, a3, bf[q][2], bf[q][3]);
                }
            }
        }

        __syncthreads();   // all warps done reading this stage
        if (tid == 0 && kt + 2 < NT) {
            const uint32_t mb = mbarBase + stage * 8;
            mbar_expect(mb, 2 * TILE_BYTES);
            bulk_g2s(kB, kg + (size_t)(kt + 2) * TILE_HALVES, TILE_BYTES, mb);
            bulk_g2s(vB, vg + (size_t)(kt + 2) * TILE_HALVES, TILE_BYTES, mb);
        }
    }

    // ---- Epilogue (l already quad-reduced by the ones-MMA) ----
    const float inv0 = 1.0f / l0;
    const float inv1 = 1.0f / l1;

    const size_t r0 = (size_t)qbase + warp * 16 + (lane >> 2);
    float* og0 = O + r0 * QS + (size_t)b * HQ * DH + (size_t)h * DH + (lane & 3) * 2;
    float* og1 = og0 + (size_t)8 * QS;
    #pragma unroll
    for (int n = 0; n < 16; n++) {
        *(float2*)(og0 + n * 8) = make_float2(acc[n][0] * inv0, acc[n][1] * inv0);
        *(float2*)(og1 + n * 8) = make_float2(acc[n][2] * inv1, acc[n][3] * inv1);
    }
}

extern "C" void kernel_launch(void* const* d_in, const int* in_sizes, int n_in,
                              void* d_out, int out_size)
{
    const float* Q = (const float*)d_in[0];
    const float* K = (const float*)d_in[1];
    const float* V = (const float*)d_in[2];
    float* O = (float*)d_out;

    convert_kv_kernel<<<KV_HALVES / 8 / 256, 256>>>(K, V);

    cudaFuncSetAttribute(fa_hmma6_kernel,
                         cudaFuncAttributeMaxDynamicSharedMemorySize,
                         (int)SMEM_BYTES);
    dim3 grid(S_LEN / BM, HQ, BATCH);  // (16, 32, 2) = 1024 CTAs
    fa_hmma6_kernel<<<grid, NTHREADS, SMEM_BYTES>>>(Q, O);
}

// round 10
// speedup vs baseline: 15.7108x; 1.0682x over previous
#include <cuda_runtime.h>
#include <cuda_fp16.h>
#include <cstdint>

// Problem constants: S=2048, B=2, HQ=32, HKV=8, D=128
#define S_LEN 2048
#define BATCH 2
#define HQ 32
#define HKV 8
#define DH 128
#define GROUP 4
// 1/sqrt(128) * log2(e)  — logits land in exp2 domain
#define QSCALE 0.1275325340386934f

#define BM 64                // query tile (4 warps x 16 rows)
#define BN 64                // key tile
#define NTHREADS 128

#define QS (BATCH * HQ * DH)   // 8192 floats per seq step (Q/O)

#define TILE_HALVES 8192       // 64 rows x 128 halves = 16KB
#define TILE_BYTES  16384
#define HEAD_TILES  (S_LEN / BN)   // 32
#define KV_HALVES (S_LEN * BATCH * HKV * DH)

// fp16 K/V, per-head contiguous, blocked-atom SW128 pre-swizzled 16KB tiles
__device__ __align__(1024) __half g_Kh[KV_HALVES];
__device__ __align__(1024) __half g_Vh[KV_HALVES];

// smem: [K0 | V0 | K1 | V1] 16KB each; ctrl (2 mbarriers) at +64KB
#define SMEM_BYTES (4 * TILE_BYTES + 16)

#define ONES2 0x3C003C00u    // half2(1.0, 1.0)

// Blocked-atom SW128 byte offset inside a 64x128-half (16KB) tile.
// atom = 8 rows x 64 halves (1KB); 8 row-atoms; col-atom 1 at +8KB.
__host__ __device__ __forceinline__ uint32_t swa64(int row, int colH) {
    return (uint32_t)((((row >> 3) + ((colH >> 6) << 3)) << 10)
                      + ((row & 7) << 7)
                      + (((colH & 63) << 1) ^ ((row & 7) << 4)));
}

__device__ __forceinline__ uint32_t smem_u32(const void* p) {
    uint32_t a;
    asm("{ .reg .u64 t; cvta.to.shared.u64 t, %1; cvt.u32.u64 %0, t; }"
        : "=r"(a) : "l"(p));
    return a;
}
__device__ __forceinline__ void bulk_g2s(uint32_t dst, const void* src,
                                         uint32_t bytes, uint32_t mbar) {
    asm volatile(
        "cp.async.bulk.shared::cta.global.mbarrier::complete_tx::bytes [%0], [%1], %2, [%3];"
        :: "r"(dst), "l"(src), "r"(bytes), "r"(mbar) : "memory");
}
__device__ __forceinline__ void mbar_init(uint32_t a, uint32_t cnt) {
    asm volatile("mbarrier.init.shared.b64 [%0], %1;" :: "r"(a), "r"(cnt) : "memory");
}
__device__ __forceinline__ void mbar_expect(uint32_t a, uint32_t tx) {
    asm volatile("mbarrier.arrive.expect_tx.shared.b64 _, [%0], %1;"
                 :: "r"(a), "r"(tx) : "memory");
}
__device__ __forceinline__ void mbar_wait(uint32_t a, uint32_t phase) {
    asm volatile(
        "{\n\t"
        ".reg .pred P;\n\t"
        "WL_%=:\n\t"
        "mbarrier.try_wait.parity.acquire.cta.shared::cta.b64 P, [%0], %1, 0x989680;\n\t"
        "@P bra.uni WD_%=;\n\t"
        "bra.uni WL_%=;\n\t"
        "WD_%=:\n\t"
        "}"
        :: "r"(a), "r"(phase) : "memory");
}
__device__ __forceinline__ void ldsm_x4(uint32_t& r0, uint32_t& r1, uint32_t& r2,
                                        uint32_t& r3, uint32_t a) {
    asm("ldmatrix.sync.aligned.m8n8.x4.shared.b16 {%0,%1,%2,%3}, [%4];"
        : "=r"(r0), "=r"(r1), "=r"(r2), "=r"(r3) : "r"(a) : "memory");
}
__device__ __forceinline__ void ldsm_x4t(uint32_t& r0, uint32_t& r1, uint32_t& r2,
                                         uint32_t& r3, uint32_t a) {
    asm("ldmatrix.sync.aligned.m8n8.x4.trans.shared.b16 {%0,%1,%2,%3}, [%4];"
        : "=r"(r0), "=r"(r1), "=r"(r2), "=r"(r3) : "r"(a) : "memory");
}
__device__ __forceinline__ void mma16816(float& c0, float& c1, float& c2, float& c3,
                                         uint32_t a0, uint32_t a1, uint32_t a2,
                                         uint32_t a3, uint32_t b0, uint32_t b1) {
    asm("mma.sync.aligned.m16n8k16.row.col.f32.f16.f16.f32 "
        "{%0,%1,%2,%3}, {%4,%5,%6,%7}, {%8,%9}, {%0,%1,%2,%3};"
        : "+f"(c0), "+f"(c1), "+f"(c2), "+f"(c3)
        : "r"(a0), "r"(a1), "r"(a2), "r"(a3), "r"(b0), "r"(b1));
}
__device__ __forceinline__ uint32_t h2u(__half2 h) {
    return *reinterpret_cast<uint32_t*>(&h);
}
__device__ __forceinline__ uint32_t ex2h2(uint32_t x) {
    uint32_t r;
    asm("ex2.approx.f16x2 %0, %1;" : "=r"(r) : "r"(x));
    return r;
}

// ---- Pre-pass: fp32 K,V -> fp16, per-head contiguous, pre-swizzled 16KB tiles ----
__global__ void __launch_bounds__(256)
convert_kv_kernel(const float* __restrict__ K, const float* __restrict__ V)
{
    const int cid = blockIdx.x * 256 + threadIdx.x;  // one 16B chunk each
    const int c8 = cid & 15;
    const int h  = (cid >> 4) & 7;
    const int b  = (cid >> 7) & 1;
    const int s  = cid >> 8;

    const size_t src = (((size_t)s * BATCH + b) * HKV + h) * DH + c8 * 8;
    float4 k0 = *(const float4*)(K + src);
    float4 k1 = *(const float4*)(K + src + 4);
    float4 v0 = *(const float4*)(V + src);
    float4 v1 = *(const float4*)(V + src + 4);

    uint4 kp, vp;
    kp.x = h2u(__floats2half2_rn(k0.x, k0.y));
    kp.y = h2u(__floats2half2_rn(k0.z, k0.w));
    kp.z = h2u(__floats2half2_rn(k1.x, k1.y));
    kp.w = h2u(__floats2half2_rn(k1.z, k1.w));
    vp.x = h2u(__floats2half2_rn(v0.x, v0.y));
    vp.y = h2u(__floats2half2_rn(v0.z, v0.w));
    vp.z = h2u(__floats2half2_rn(v1.x, v1.y));
    vp.w = h2u(__floats2half2_rn(v1.z, v1.w));

    const size_t headB = ((size_t)b * HKV + h) * (HEAD_TILES * TILE_BYTES);
    const size_t off = headB + (size_t)(s >> 6) * TILE_BYTES + swa64(s & 63, c8 * 8);
    *(uint4*)((char*)g_Kh + off) = kp;
    *(uint4*)((char*)g_Vh + off) = vp;
}

__global__ void __launch_bounds__(NTHREADS, 3)
fa_hmma7_kernel(const float* __restrict__ Q, float* __restrict__ O)
{
    extern __shared__ __half sm[];
    const uint32_t smBase = smem_u32(sm);

    const int tid = threadIdx.x;
    const int warp = tid >> 5;
    const int lane = tid & 31;

    const int qblock = (S_LEN / BM - 1) - blockIdx.x;  // heavy blocks first
    const int h = blockIdx.y, b = blockIdx.z;
    const int hk = h / GROUP;
    const int qbase = qblock * BM;
    const int NT = qblock + 1;

    const __half* kg = g_Kh + ((size_t)b * HKV + hk) * (HEAD_TILES * TILE_HALVES);
    const __half* vg = g_Vh + ((size_t)b * HKV + hk) * (HEAD_TILES * TILE_HALVES);

    const uint32_t kStage[2] = { smBase,                   smBase + 2u * TILE_BYTES };
    const uint32_t vStage[2] = { smBase + 1u * TILE_BYTES, smBase + 3u * TILE_BYTES };
    const uint32_t mbarBase = smBase + 4u * TILE_BYTES;

    if (tid == 0) {
        mbar_init(mbarBase, 1);
        mbar_init(mbarBase + 8, 1);
    }

    // ---- Stage Q (fp32 -> scaled fp16) into K0 region (swa64 layout); ldsm to regs ----
    uint32_t qa[8][4];
    {
        const float* qg = Q + (size_t)qbase * QS + (size_t)b * HQ * DH + (size_t)h * DH;
        #pragma unroll
        for (int i = 0; i < 8; i++) {
            int e = tid + i * NTHREADS;         // 1024 chunks: row = e>>4, c8 = e&15
            int r = e >> 4, c8 = e & 15;
            float4 v0 = *(const float4*)(qg + (size_t)r * QS + c8 * 8);
            float4 v1 = *(const float4*)(qg + (size_t)r * QS + c8 * 8 + 4);
            uint4 p;
            p.x = h2u(__floats2half2_rn(v0.x * QSCALE, v0.y * QSCALE));
            p.y = h2u(__floats2half2_rn(v0.z * QSCALE, v0.w * QSCALE));
            p.z = h2u(__floats2half2_rn(v1.x * QSCALE, v1.y * QSCALE));
            p.w = h2u(__floats2half2_rn(v1.z * QSCALE, v1.w * QSCALE));
            *(uint4*)((char*)sm + swa64(r, c8 * 8)) = p;
        }
        __syncthreads();   // Q staged + mbar init visible
        const int qRow = warp * 16 + (lane & 15);
        const int qCol = (lane >> 4) * 8;
        #pragma unroll
        for (int kk = 0; kk < 8; kk++)
            ldsm_x4(qa[kk][0], qa[kk][1], qa[kk][2], qa[kk][3],
                    smBase + swa64(qRow, kk * 16 + qCol));
        __syncthreads();   // Q reads done before bulk copies overwrite K0
    }

    // ---- Prologue: bulk-prefetch tiles 0 and 1 ----
    if (tid == 0) {
        #pragma unroll
        for (int t = 0; t < 2; t++) {
            if (t < NT) {
                const uint32_t mb = mbarBase + t * 8;
                mbar_expect(mb, 2 * TILE_BYTES);
                bulk_g2s(kStage[t], kg + (size_t)t * TILE_HALVES, TILE_BYTES, mb);
                bulk_g2s(vStage[t], vg + (size_t)t * TILE_HALVES, TILE_BYTES, mb);
            }
        }
    }

    float acc[16][4];
    #pragma unroll
    for (int n = 0; n < 16; n++)
        #pragma unroll
        for (int c = 0; c < 4; c++) acc[n][c] = 0.0f;
    float m0 = -1e30f, m1 = -1e30f, l0 = 0.0f, l1 = 0.0f;

    const int mrow0 = warp * 16 + (lane >> 2);
    const int mcol0 = (lane & 3) * 2;
    const int kRowL = (lane & 7) + ((lane >> 4) << 3);
    const int kColL = (((lane & 15) >> 3) << 3);
    const int vRowL = (lane & 15);
    const int vColL = ((lane >> 4) << 3);

    for (int kt = 0; kt < NT; kt++) {
        const int stage = kt & 1;
        mbar_wait(mbarBase + stage * 8, (kt >> 1) & 1);

        const uint32_t kB = kStage[stage];
        const uint32_t vB = vStage[stage];
        const bool diag = (kt == qblock);

        // ---- S = Q K^T : 8 k-steps x 4 j-pairs (64 keys) ----
        float sc[8][4];
        #pragma unroll
        for (int j = 0; j < 8; j++)
            #pragma unroll
            for (int c = 0; c < 4; c++) sc[j][c] = 0.0f;
        #pragma unroll
        for (int kk = 0; kk < 8; kk++) {
            uint32_t bf[4][4];
            #pragma unroll
            for (int jp = 0; jp < 4; jp++)
                ldsm_x4(bf[jp][0], bf[jp][1], bf[jp][2], bf[jp][3],
                        kB + swa64(jp * 16 + kRowL, kk * 16 + kColL));
            #pragma unroll
            for (int jp = 0; jp < 4; jp++) {
                mma16816(sc[2*jp][0], sc[2*jp][1], sc[2*jp][2], sc[2*jp][3],
                         qa[kk][0], qa[kk][1], qa[kk][2], qa[kk][3],
                         bf[jp][0], bf[jp][1]);
                mma16816(sc[2*jp+1][0], sc[2*jp+1][1], sc[2*jp+1][2], sc[2*jp+1][3],
                         qa[kk][0], qa[kk][1], qa[kk][2], qa[kk][3],
                         bf[jp][2], bf[jp][3]);
            }
        }

        // ---- Causal mask (diagonal tile: kbase == qbase) ----
        if (diag) {
            #pragma unroll
            for (int j = 0; j < 8; j++) {
                int c = mcol0 + j * 8;
                if (c     > mrow0)     sc[j][0] = -1e30f;
                if (c + 1 > mrow0)     sc[j][1] = -1e30f;
                if (c     > mrow0 + 8) sc[j][2] = -1e30f;
                if (c + 1 > mrow0 + 8) sc[j][3] = -1e30f;
            }
        }

        // ---- Online softmax (exp2 domain, f16x2 exp) ----
        float mt0 = m0, mt1 = m1;
        #pragma unroll
        for (int j = 0; j < 8; j++) {
            mt0 = fmaxf(mt0, fmaxf(sc[j][0], sc[j][1]));
            mt1 = fmaxf(mt1, fmaxf(sc[j][2], sc[j][3]));
        }
        mt0 = fmaxf(mt0, __shfl_xor_sync(0xffffffffu, mt0, 1));
        mt0 = fmaxf(mt0, __shfl_xor_sync(0xffffffffu, mt0, 2));
        mt1 = fmaxf(mt1, __shfl_xor_sync(0xffffffffu, mt1, 1));
        mt1 = fmaxf(mt1, __shfl_xor_sync(0xffffffffu, mt1, 2));
        const float f0 = exp2f(m0 - mt0);
        const float f1 = exp2f(m1 - mt1);
        m0 = mt0; m1 = mt1;

        uint32_t ph[8][2];
        #pragma unroll
        for (int j = 0; j < 8; j++) {
            float d0 = sc[j][0] - m0, d1 = sc[j][1] - m0;
            float d2 = sc[j][2] - m1, d3 = sc[j][3] - m1;
            ph[j][0] = ex2h2(h2u(__floats2half2_rn(d0, d1)));
            ph[j][1] = ex2h2(h2u(__floats2half2_rn(d2, d3)));
        }

        // row sums via ones-MMA (also reduces across the quad)
        float rs[4] = {0.0f, 0.0f, 0.0f, 0.0f};
        #pragma unroll
        for (int kp = 0; kp < 4; kp++)
            mma16816(rs[0], rs[1], rs[2], rs[3],
                     ph[2*kp][0], ph[2*kp][1], ph[2*kp+1][0], ph[2*kp+1][1],
                     ONES2, ONES2);
        l0 = l0 * f0 + rs[0];
        l1 = l1 * f1 + rs[2];

        #pragma unroll
        for (int n = 0; n < 16; n++) {
            acc[n][0] *= f0; acc[n][1] *= f0;
            acc[n][2] *= f1; acc[n][3] *= f1;
        }

        // ---- O += P V : 4 k-steps x 8 n-pairs ----
        #pragma unroll
        for (int kk = 0; kk < 4; kk++) {
            const uint32_t a0 = ph[2*kk][0], a1 = ph[2*kk][1];
            const uint32_t a2 = ph[2*kk+1][0], a3 = ph[2*kk+1][1];
            #pragma unroll
            for (int ng = 0; ng < 2; ng++) {
                uint32_t bf[4][4];
                #pragma unroll
                for (int q = 0; q < 4; q++)
                    ldsm_x4t(bf[q][0], bf[q][1], bf[q][2], bf[q][3],
                             vB + swa64(kk * 16 + vRowL, (ng * 4 + q) * 16 + vColL));
                #pragma unroll
                for (int q = 0; q < 4; q++) {
                    const int np = ng * 4 + q;
                    mma16816(acc[2*np][0], acc[2*np][1], acc[2*np][2], acc[2*np][3],
                             a0, a1, a2, a3, bf[q][0], bf[q][1]);
                    mma16816(acc[2*np+1][0], acc[2*np+1][1], acc[2*np+1][2], acc[2*np+1][3],
                             a0, a1, a2, a3, bf[q][2], bf[q][3]);
                }
            }
        }

        __syncthreads();   // all warps done reading this stage
        if (tid == 0 && kt + 2 < NT) {
            const uint32_t mb = mbarBase + stage * 8;
            mbar_expect(mb, 2 * TILE_BYTES);
            bulk_g2s(kB, kg + (size_t)(kt + 2) * TILE_HALVES, TILE_BYTES, mb);
            bulk_g2s(vB, vg + (size_t)(kt + 2) * TILE_HALVES, TILE_BYTES, mb);
        }
    }

    // ---- Epilogue (l already quad-reduced by the ones-MMA) ----
    const float inv0 = 1.0f / l0;
    const float inv1 = 1.0f / l1;

    const size_t r0 = (size_t)qbase + warp * 16 + (lane >> 2);
    float* og0 = O + r0 * QS + (size_t)b * HQ * DH + (size_t)h * DH + (lane & 3) * 2;
    float* og1 = og0 + (size_t)8 * QS;
    #pragma unroll
    for (int n = 0; n < 16; n++) {
        *(float2*)(og0 + n * 8) = make_float2(acc[n][0] * inv0, acc[n][1] * inv0);
        *(float2*)(og1 + n * 8) = make_float2(acc[n][2] * inv1, acc[n][3] * inv1);
    }
}

extern "C" void kernel_launch(void* const* d_in, const int* in_sizes, int n_in,
                              void* d_out, int out_size)
{
    const float* Q = (const float*)d_in[0];
    const float* K = (const float*)d_in[1];
    const float* V = (const float*)d_in[2];
    float* O = (float*)d_out;

    convert_kv_kernel<<<KV_HALVES / 8 / 256, 256>>>(K, V);

    cudaFuncSetAttribute(fa_hmma7_kernel,
                         cudaFuncAttributeMaxDynamicSharedMemorySize,
                         (int)SMEM_BYTES);
    dim3 grid(S_LEN / BM, HQ, BATCH);  // (32, 32, 2) = 2048 CTAs
    fa_hmma7_kernel<<<grid, NTHREADS, SMEM_BYTES>>>(Q, O);
}